// round 7
// baseline (speedup 1.0000x reference)
#include <cuda_runtime.h>
#include <cstdint>

#define N_NODES 20000
#define N_EDGES 640000
#define FEAT 8
#define OUT 64
#define PERIODS 12
#define XDIM (FEAT * PERIODS)   // 96
#define CAP 128                 // per-node in-edge bucket capacity
#define NB 68                   // nodes per fused block
#define NTHR 272                // NB*64/16

typedef unsigned long long u64;

// ---------------- scratch (no allocation allowed) ----------------
__device__ __align__(16) int   g_cursor[N_NODES];
__device__ __align__(16) int   g_srcs[N_NODES * CAP];    // src ids bucketed by dst
__device__ __align__(16) float g_xs[N_NODES * XDIM];     // dinv[i] * x[i], t-major rows
__device__ __align__(16) float g_Ax[N_NODES * XDIM];     // A_norm @ x, t-major rows
__device__ __align__(16) float g_WP[3 * FEAT * OUT];     // combined W_g @ L_g_top
__device__ __align__(16) float g_BP[3 * OUT];            // combined biases
__device__ float g_probs[PERIODS];

// ---------------- helpers ----------------
__device__ __forceinline__ float sigf(float v) {
    return __fdividef(1.0f, 1.0f + __expf(-v));
}
__device__ __forceinline__ float tanhfast(float v) {
    return 2.0f * __fdividef(1.0f, 1.0f + __expf(-2.0f * v)) - 1.0f;
}
__device__ __forceinline__ u64 packdup(float a) {
    u64 r;
    asm("mov.b64 %0, {%1, %2};" : "=l"(r) : "r"(__float_as_uint(a)), "r"(__float_as_uint(a)));
    return r;
}
__device__ __forceinline__ u64 pack2(float a, float b) {
    u64 r;
    asm("mov.b64 %0, {%1, %2};" : "=l"(r) : "r"(__float_as_uint(a)), "r"(__float_as_uint(b)));
    return r;
}
__device__ __forceinline__ void unpack2(u64 v, float& a, float& b) {
    unsigned lo, hi;
    asm("mov.b64 {%0, %1}, %2;" : "=r"(lo), "=r"(hi) : "l"(v));
    a = __uint_as_float(lo);
    b = __uint_as_float(hi);
}
__device__ __forceinline__ u64 fma2(u64 a, u64 b, u64 c) {
    u64 d;
    asm("fma.rn.f32x2 %0, %1, %2, %3;" : "=l"(d) : "l"(a), "l"(b), "l"(c));
    return d;
}

// ---------------- K1: zero cursors ----------------
__global__ void k_zero() {
    int i = blockIdx.x * blockDim.x + threadIdx.x;
    if (i < N_NODES) g_cursor[i] = 0;
}

// ---------------- K2: fill buckets (cursor doubles as in-degree) ------------
__global__ void k_fill(const int* __restrict__ ei) {
    int e = blockIdx.x * blockDim.x + threadIdx.x;
    if (e >= N_EDGES) return;
    int s = ei[e];
    int d = ei[N_EDGES + e];
    int pos = atomicAdd(&g_cursor[d], 1);
    if (pos < CAP) g_srcs[d * CAP + pos] = s;
}

// ---------------- K3: transpose x to t-major + pre-scale by dinv[src] -------
__global__ void k_scale(const float* __restrict__ x) {
    int idx = blockIdx.x * blockDim.x + threadIdx.x;
    if (idx >= N_NODES * XDIM) return;
    int node = idx / XDIM;
    int r = idx - node * XDIM;          // r = t*8 + f (t-major output)
    int t = r >> 3, f = r & 7;
    float v = x[node * XDIM + f * PERIODS + t];
    float dinv = rsqrtf((float)g_cursor[node] + 1.0f);
    g_xs[idx] = v * dinv;
}

// ---------------- K4: gather, one warp per node ----------------
__global__ void __launch_bounds__(256) k_gather() {
    int gw = (blockIdx.x * 256 + threadIdx.x) >> 5;   // global warp = node
    if (gw >= N_NODES) return;
    int lane = threadIdx.x & 31;
    int node = gw;
    int deg = g_cursor[node];
    int ndeg = min(deg, CAP);
    const int* bucket = g_srcs + node * CAP;
    float a0 = 0.f, a1 = 0.f, a2 = 0.f;
    for (int j0 = 0; j0 < ndeg; j0 += 32) {
        int sj = (j0 + lane < ndeg) ? bucket[j0 + lane] : 0;
        int lim = min(32, ndeg - j0);
#pragma unroll 4
        for (int jj = 0; jj < lim; jj++) {
            int s = __shfl_sync(0xffffffffu, sj, jj);
            const float* row = g_xs + s * XDIM;
            a0 += row[lane];
            a1 += row[lane + 32];
            a2 += row[lane + 64];
        }
    }
    const float* self = g_xs + node * XDIM;   // has dinv[node] folded already
    float dd = rsqrtf((float)deg + 1.0f);
    float* dst = g_Ax + node * XDIM;
    dst[lane]      = dd * (a0 + self[lane]);
    dst[lane + 32] = dd * (a1 + self[lane + 32]);
    dst[lane + 64] = dd * (a2 + self[lane + 64]);
}

// ---------------- K5: folded weights + softmax ----------------
__global__ void k_pre(const float* Wz, const float* bz, const float* Lz, const float* Lzb,
                      const float* Wr, const float* br, const float* Lr, const float* Lrb,
                      const float* Wh, const float* bh, const float* Lh, const float* Lhb,
                      const float* att) {
    const float* W[3] = {Wz, Wr, Wh};
    const float* L[3] = {Lz, Lr, Lh};
    const float* B[3] = {bz, br, bh};
    const float* LB[3] = {Lzb, Lrb, Lhb};
    int tid = threadIdx.x;
    for (int idx = tid; idx < 3 * FEAT * OUT; idx += blockDim.x) {
        int g = idx / (FEAT * OUT);
        int r = idx - g * (FEAT * OUT);
        int f = r / OUT, o = r - (r / OUT) * OUT;
        float s = 0.0f;
        for (int k = 0; k < OUT; k++) s = fmaf(W[g][f * OUT + k], L[g][k * OUT + o], s);
        g_WP[idx] = s;
    }
    for (int idx = tid; idx < 3 * OUT; idx += blockDim.x) {
        int g = idx / OUT, o = idx - (idx / OUT) * OUT;
        float s = LB[g][o];
        for (int k = 0; k < OUT; k++) s = fmaf(B[g][k], L[g][k * OUT + o], s);
        g_BP[idx] = s;
    }
    if (tid == 0) {
        float m = att[0];
        for (int t = 1; t < PERIODS; t++) m = fmaxf(m, att[t]);
        float e[PERIODS], sum = 0.0f;
        for (int t = 0; t < PERIODS; t++) { e[t] = __expf(att[t] - m); sum += e[t]; }
        float inv = __fdividef(1.0f, sum);
        for (int t = 0; t < PERIODS; t++) g_probs[t] = e[t] * inv;
    }
}

// ---------------- K6: fused 12-step GRU + head ----------------
struct FSmem {
    float4 LB[3][OUT][16];   // 48 KB: bottom halves of L (gates z,r,h)
    float4 WP[3][FEAT][16];  // 6 KB (head reuses as sW)
    float  BP[3][OUT];       // 768 B (head reuses as sB)
    float  H[NB][OUT];       // 17 KB
    union {
        float A[NB][XDIM];   // 25.5 KB
        float Hs[NB][OUT + 4];
    } u;
};

__global__ void __launch_bounds__(NTHR, 2)
k_fused(const float* __restrict__ Lz, const float* __restrict__ Lr,
        const float* __restrict__ Lh, const float* __restrict__ hw,
        const float* __restrict__ hb, float* __restrict__ out) {
    extern __shared__ char smraw[];
    FSmem* sm = reinterpret_cast<FSmem*>(smraw);
    int tid = threadIdx.x;
    int nb = blockIdx.x * NB;

    // ---- cooperative load ----
    {
        const float4* src[3] = {
            reinterpret_cast<const float4*>(Lz) + 1024,
            reinterpret_cast<const float4*>(Lr) + 1024,
            reinterpret_cast<const float4*>(Lh) + 1024};
        float4* dst = &sm->LB[0][0][0];
        for (int i = tid; i < 3 * 1024; i += NTHR) dst[i] = src[i >> 10][i & 1023];

        const float4* wp4 = reinterpret_cast<const float4*>(g_WP);
        float4* wdst = &sm->WP[0][0][0];
        for (int i = tid; i < 384; i += NTHR) wdst[i] = wp4[i];

        float* bdst = &sm->BP[0][0];
        for (int i = tid; i < 192; i += NTHR) bdst[i] = g_BP[i];

        float4* H4 = reinterpret_cast<float4*>(sm->H);
        for (int i = tid; i < NB * 16; i += NTHR) H4[i] = make_float4(0.f, 0.f, 0.f, 0.f);

        const float4* Ax4 = reinterpret_cast<const float4*>(g_Ax);
        float4* A4 = reinterpret_cast<float4*>(sm->u.A);
        for (int i = tid; i < NB * 24; i += NTHR) {
            int n = i / 24, c = i - n * 24;
            int node = nb + n;
            A4[i] = (node < N_NODES) ? Ax4[node * 24 + c] : make_float4(0.f, 0.f, 0.f, 0.f);
        }
    }
    __syncthreads();

    const int cg = tid & 15;        // column group (4 output cols)
    const int ng = (tid >> 4) * 4;  // first of this thread's 4 nodes
    const unsigned wmask = (tid >= 256) ? 0x0000ffffu : 0xffffffffu;

    float hacc[4][4];
#pragma unroll
    for (int n = 0; n < 4; n++)
#pragma unroll
        for (int c = 0; c < 4; c++) hacc[n][c] = 0.0f;

    for (int t = 0; t < PERIODS; t++) {
        float p = g_probs[t];

        // ---- phase 1: z and r gates ----
        u64 az[4][2], ar[4][2];
        {
            float4 b0 = *reinterpret_cast<const float4*>(&sm->BP[0][4 * cg]);
            float4 b1 = *reinterpret_cast<const float4*>(&sm->BP[1][4 * cg]);
#pragma unroll
            for (int n = 0; n < 4; n++) {
                az[n][0] = pack2(b0.x, b0.y); az[n][1] = pack2(b0.z, b0.w);
                ar[n][0] = pack2(b1.x, b1.y); ar[n][1] = pack2(b1.z, b1.w);
            }
        }
#pragma unroll
        for (int f = 0; f < FEAT; f++) {
            ulonglong2 wz = *reinterpret_cast<const ulonglong2*>(&sm->WP[0][f][cg]);
            ulonglong2 wr = *reinterpret_cast<const ulonglong2*>(&sm->WP[1][f][cg]);
#pragma unroll
            for (int n = 0; n < 4; n++) {
                u64 s = packdup(sm->u.A[ng + n][t * 8 + f]);
                az[n][0] = fma2(s, wz.x, az[n][0]); az[n][1] = fma2(s, wz.y, az[n][1]);
                ar[n][0] = fma2(s, wr.x, ar[n][0]); ar[n][1] = fma2(s, wr.y, ar[n][1]);
            }
        }
        for (int k0 = 0; k0 < OUT; k0 += 4) {
            float hv[4][4];
#pragma unroll
            for (int n = 0; n < 4; n++) {
                float4 h4 = *reinterpret_cast<const float4*>(&sm->H[ng + n][k0]);
                hv[n][0] = h4.x; hv[n][1] = h4.y; hv[n][2] = h4.z; hv[n][3] = h4.w;
            }
#pragma unroll
            for (int kk = 0; kk < 4; kk++) {
                ulonglong2 wz = *reinterpret_cast<const ulonglong2*>(&sm->LB[0][k0 + kk][cg]);
                ulonglong2 wr = *reinterpret_cast<const ulonglong2*>(&sm->LB[1][k0 + kk][cg]);
#pragma unroll
                for (int n = 0; n < 4; n++) {
                    u64 s = packdup(hv[n][kk]);
                    az[n][0] = fma2(s, wz.x, az[n][0]); az[n][1] = fma2(s, wz.y, az[n][1]);
                    ar[n][0] = fma2(s, wr.x, ar[n][0]); ar[n][1] = fma2(s, wr.y, ar[n][1]);
                }
            }
        }

        float zf[4][4], holdv[4][4];
#pragma unroll
        for (int n = 0; n < 4; n++) {
            float v0, v1, v2, v3;
            unpack2(az[n][0], v0, v1); unpack2(az[n][1], v2, v3);
            zf[n][0] = sigf(v0); zf[n][1] = sigf(v1); zf[n][2] = sigf(v2); zf[n][3] = sigf(v3);
            float4 hd = *reinterpret_cast<const float4*>(&sm->H[ng + n][4 * cg]);
            holdv[n][0] = hd.x; holdv[n][1] = hd.y; holdv[n][2] = hd.z; holdv[n][3] = hd.w;
        }
        __syncwarp(wmask);   // S1: phase-1 reads of H done
#pragma unroll
        for (int n = 0; n < 4; n++) {
            float v0, v1, v2, v3;
            unpack2(ar[n][0], v0, v1); unpack2(ar[n][1], v2, v3);
            float4 hr;
            hr.x = sigf(v0) * holdv[n][0];
            hr.y = sigf(v1) * holdv[n][1];
            hr.z = sigf(v2) * holdv[n][2];
            hr.w = sigf(v3) * holdv[n][3];
            *reinterpret_cast<float4*>(&sm->H[ng + n][4 * cg]) = hr;   // H := H*R
        }
        __syncwarp(wmask);   // S2: HR visible

        // ---- phase 2: h gate ----
        u64 ah[4][2];
        {
            float4 b2 = *reinterpret_cast<const float4*>(&sm->BP[2][4 * cg]);
#pragma unroll
            for (int n = 0; n < 4; n++) {
                ah[n][0] = pack2(b2.x, b2.y); ah[n][1] = pack2(b2.z, b2.w);
            }
        }
#pragma unroll
        for (int f = 0; f < FEAT; f++) {
            ulonglong2 wh = *reinterpret_cast<const ulonglong2*>(&sm->WP[2][f][cg]);
#pragma unroll
            for (int n = 0; n < 4; n++) {
                u64 s = packdup(sm->u.A[ng + n][t * 8 + f]);
                ah[n][0] = fma2(s, wh.x, ah[n][0]); ah[n][1] = fma2(s, wh.y, ah[n][1]);
            }
        }
        for (int k0 = 0; k0 < OUT; k0 += 4) {
            float hv[4][4];
#pragma unroll
            for (int n = 0; n < 4; n++) {
                float4 h4 = *reinterpret_cast<const float4*>(&sm->H[ng + n][k0]);
                hv[n][0] = h4.x; hv[n][1] = h4.y; hv[n][2] = h4.z; hv[n][3] = h4.w;
            }
#pragma unroll
            for (int kk = 0; kk < 4; kk++) {
                ulonglong2 wh = *reinterpret_cast<const ulonglong2*>(&sm->LB[2][k0 + kk][cg]);
#pragma unroll
                for (int n = 0; n < 4; n++) {
                    u64 s = packdup(hv[n][kk]);
                    ah[n][0] = fma2(s, wh.x, ah[n][0]); ah[n][1] = fma2(s, wh.y, ah[n][1]);
                }
            }
        }

        float hnv[4][4];
#pragma unroll
        for (int n = 0; n < 4; n++) {
            float v0, v1, v2, v3;
            unpack2(ah[n][0], v0, v1); unpack2(ah[n][1], v2, v3);
            float ht[4] = {tanhfast(v0), tanhfast(v1), tanhfast(v2), tanhfast(v3)};
#pragma unroll
            for (int c = 0; c < 4; c++) {
                float hn = zf[n][c] * holdv[n][c] + (1.0f - zf[n][c]) * ht[c];
                hnv[n][c] = hn;
                hacc[n][c] = fmaf(p, hn, hacc[n][c]);
            }
        }
        __syncwarp(wmask);   // S3: phase-2 reads done
#pragma unroll
        for (int n = 0; n < 4; n++) {
            *reinterpret_cast<float4*>(&sm->H[ng + n][4 * cg]) =
                make_float4(hnv[n][0], hnv[n][1], hnv[n][2], hnv[n][3]);
        }
        __syncwarp(wmask);   // S4: new H visible
    }

    // ---- fused head: out = relu(Hacc) @ head_W + head_b ----
    __syncthreads();   // CRITICAL: all warps done reading u.A before Hs overwrites it

#pragma unroll
    for (int n = 0; n < 4; n++)
#pragma unroll
        for (int c = 0; c < 4; c++)
            sm->u.Hs[ng + n][4 * cg + c] = fmaxf(hacc[n][c], 0.0f);

    __syncthreads();   // Hs visible; all done with WP/BP before overwrite

    float* sW = &sm->WP[0][0][0].x;   // reuse: 768 floats
    float* sB = &sm->BP[0][0];
    for (int i = tid; i < OUT * PERIODS; i += NTHR) sW[i] = hw[i];
    if (tid < PERIODS) sB[tid] = hb[tid];
    __syncthreads();

    for (int i = tid; i < NB * PERIODS; i += NTHR) {
        int nn = i / PERIODS;
        int pp = i - nn * PERIODS;
        int node = nb + nn;
        if (node < N_NODES) {
            float acc = sB[pp];
#pragma unroll 16
            for (int o = 0; o < OUT; o++)
                acc = fmaf(sm->u.Hs[nn][o], sW[o * PERIODS + pp], acc);
            out[node * PERIODS + pp] = acc;
        }
    }
}

// ---------------- launch ----------------
extern "C" void kernel_launch(void* const* d_in, const int* in_sizes, int n_in,
                              void* d_out, int out_size) {
    const float* x    = (const float*)d_in[0];
    const int*   ei   = (const int*)d_in[1];
    const float* Wz   = (const float*)d_in[2];
    const float* bz   = (const float*)d_in[3];
    const float* LzW  = (const float*)d_in[4];
    const float* Lzb  = (const float*)d_in[5];
    const float* Wr   = (const float*)d_in[6];
    const float* br   = (const float*)d_in[7];
    const float* LrW  = (const float*)d_in[8];
    const float* Lrb  = (const float*)d_in[9];
    const float* Wh   = (const float*)d_in[10];
    const float* bh   = (const float*)d_in[11];
    const float* LhW  = (const float*)d_in[12];
    const float* Lhb  = (const float*)d_in[13];
    const float* att  = (const float*)d_in[14];
    const float* hW   = (const float*)d_in[15];
    const float* hb   = (const float*)d_in[16];
    float* out = (float*)d_out;

    cudaFuncSetAttribute(k_fused, cudaFuncAttributeMaxDynamicSharedMemorySize,
                         (int)sizeof(FSmem));

    k_zero<<<(N_NODES + 255) / 256, 256>>>();
    k_fill<<<(N_EDGES + 255) / 256, 256>>>(ei);
    k_pre<<<1, 256>>>(Wz, bz, LzW, Lzb, Wr, br, LrW, Lrb, Wh, bh, LhW, Lhb, att);
    k_scale<<<(N_NODES * XDIM + 255) / 256, 256>>>(x);
    k_gather<<<(N_NODES * 32 + 255) / 256, 256>>>();

    k_fused<<<(N_NODES + NB - 1) / NB, NTHR, sizeof(FSmem)>>>(LzW, LrW, LhW, hW, hb, out);
}

// round 8
// speedup vs baseline: 1.0009x; 1.0009x over previous
#include <cuda_runtime.h>
#include <cstdint>

#define N_NODES 20000
#define N_EDGES 640000
#define FEAT 8
#define OUT 64
#define PERIODS 12
#define XDIM (FEAT * PERIODS)   // 96
#define CAP 128                 // per-node in-edge bucket capacity
#define NB 68                   // nodes per fused block
#define NTHR 272                // NB*64/16

typedef unsigned long long u64;

// ---------------- scratch (no allocation allowed) ----------------
__device__ __align__(16) int   g_cursor[N_NODES];
__device__ __align__(16) int   g_srcs[N_NODES * CAP];    // src ids bucketed by dst
__device__ __align__(16) float g_xs[N_NODES * XDIM];     // dinv[i] * x[i], t-major rows
__device__ __align__(16) float g_Ax[N_NODES * XDIM];     // A_norm @ x, t-major rows
__device__ __align__(16) float g_WP[3 * FEAT * OUT];     // combined W_g @ L_g_top
__device__ __align__(16) float g_BP[3 * OUT];            // combined biases
__device__ float g_probs[PERIODS];

// ---------------- helpers ----------------
__device__ __forceinline__ float sigf(float v) {
    return __fdividef(1.0f, 1.0f + __expf(-v));
}
__device__ __forceinline__ float tanhfast(float v) {
    return 2.0f * __fdividef(1.0f, 1.0f + __expf(-2.0f * v)) - 1.0f;
}
__device__ __forceinline__ u64 packdup(float a) {
    u64 r;
    asm("mov.b64 %0, {%1, %2};" : "=l"(r) : "r"(__float_as_uint(a)), "r"(__float_as_uint(a)));
    return r;
}
__device__ __forceinline__ u64 pack2(float a, float b) {
    u64 r;
    asm("mov.b64 %0, {%1, %2};" : "=l"(r) : "r"(__float_as_uint(a)), "r"(__float_as_uint(b)));
    return r;
}
__device__ __forceinline__ void unpack2(u64 v, float& a, float& b) {
    unsigned lo, hi;
    asm("mov.b64 {%0, %1}, %2;" : "=r"(lo), "=r"(hi) : "l"(v));
    a = __uint_as_float(lo);
    b = __uint_as_float(hi);
}
__device__ __forceinline__ u64 fma2(u64 a, u64 b, u64 c) {
    u64 d;
    asm("fma.rn.f32x2 %0, %1, %2, %3;" : "=l"(d) : "l"(a), "l"(b), "l"(c));
    return d;
}

// ---------------- K1: zero cursors ----------------
__global__ void k_zero() {
    int i = blockIdx.x * blockDim.x + threadIdx.x;
    if (i < N_NODES) g_cursor[i] = 0;
}

// ---------------- K2: fill buckets (cursor doubles as in-degree) ------------
__global__ void k_fill(const int* __restrict__ ei) {
    int e = blockIdx.x * blockDim.x + threadIdx.x;
    if (e >= N_EDGES) return;
    int s = ei[e];
    int d = ei[N_EDGES + e];
    int pos = atomicAdd(&g_cursor[d], 1);
    if (pos < CAP) g_srcs[d * CAP + pos] = s;
}

// ---------------- K3: transpose x to t-major + pre-scale by dinv[src] -------
__global__ void k_scale(const float* __restrict__ x) {
    int idx = blockIdx.x * blockDim.x + threadIdx.x;
    if (idx >= N_NODES * XDIM) return;
    int node = idx / XDIM;
    int r = idx - node * XDIM;          // r = t*8 + f (t-major output)
    int t = r >> 3, f = r & 7;
    float v = x[node * XDIM + f * PERIODS + t];
    float dinv = rsqrtf((float)g_cursor[node] + 1.0f);
    g_xs[idx] = v * dinv;
}

// ---------------- K4: gather, one warp per node ----------------
__global__ void __launch_bounds__(256) k_gather() {
    int gw = (blockIdx.x * 256 + threadIdx.x) >> 5;   // global warp = node
    if (gw >= N_NODES) return;
    int lane = threadIdx.x & 31;
    int node = gw;
    int deg = g_cursor[node];
    int ndeg = min(deg, CAP);
    const int* bucket = g_srcs + node * CAP;
    float a0 = 0.f, a1 = 0.f, a2 = 0.f;
    for (int j0 = 0; j0 < ndeg; j0 += 32) {
        int sj = (j0 + lane < ndeg) ? bucket[j0 + lane] : 0;
        int lim = min(32, ndeg - j0);
#pragma unroll 4
        for (int jj = 0; jj < lim; jj++) {
            int s = __shfl_sync(0xffffffffu, sj, jj);
            const float* row = g_xs + s * XDIM;
            a0 += row[lane];
            a1 += row[lane + 32];
            a2 += row[lane + 64];
        }
    }
    const float* self = g_xs + node * XDIM;   // has dinv[node] folded already
    float dd = rsqrtf((float)deg + 1.0f);
    float* dst = g_Ax + node * XDIM;
    dst[lane]      = dd * (a0 + self[lane]);
    dst[lane + 32] = dd * (a1 + self[lane + 32]);
    dst[lane + 64] = dd * (a2 + self[lane + 64]);
}

// ---------------- K5: folded weights + softmax ----------------
__global__ void k_pre(const float* Wz, const float* bz, const float* Lz, const float* Lzb,
                      const float* Wr, const float* br, const float* Lr, const float* Lrb,
                      const float* Wh, const float* bh, const float* Lh, const float* Lhb,
                      const float* att) {
    const float* W[3] = {Wz, Wr, Wh};
    const float* L[3] = {Lz, Lr, Lh};
    const float* B[3] = {bz, br, bh};
    const float* LB[3] = {Lzb, Lrb, Lhb};
    int tid = threadIdx.x;
    for (int idx = tid; idx < 3 * FEAT * OUT; idx += blockDim.x) {
        int g = idx / (FEAT * OUT);
        int r = idx - g * (FEAT * OUT);
        int f = r / OUT, o = r - (r / OUT) * OUT;
        float s = 0.0f;
        for (int k = 0; k < OUT; k++) s = fmaf(W[g][f * OUT + k], L[g][k * OUT + o], s);
        g_WP[idx] = s;
    }
    for (int idx = tid; idx < 3 * OUT; idx += blockDim.x) {
        int g = idx / OUT, o = idx - (idx / OUT) * OUT;
        float s = LB[g][o];
        for (int k = 0; k < OUT; k++) s = fmaf(B[g][k], L[g][k * OUT + o], s);
        g_BP[idx] = s;
    }
    if (tid == 0) {
        float m = att[0];
        for (int t = 1; t < PERIODS; t++) m = fmaxf(m, att[t]);
        float e[PERIODS], sum = 0.0f;
        for (int t = 0; t < PERIODS; t++) { e[t] = __expf(att[t] - m); sum += e[t]; }
        float inv = __fdividef(1.0f, sum);
        for (int t = 0; t < PERIODS; t++) g_probs[t] = e[t] * inv;
    }
}

// ---------------- K6: fused 12-step GRU + head ----------------
struct FSmem {
    float4 LB[3][OUT][16];   // 48 KB: bottom halves of L (gates z,r,h)
    float4 WP[3][FEAT][16];  // 6 KB (head reuses as sW)
    float  BP[3][OUT];       // 768 B (head reuses as sB)
    float  H[NB][OUT];       // 17 KB
    union {
        float A[NB][XDIM];   // 25.5 KB
        float Hs[NB][OUT + 4];
    } u;
};

__global__ void __launch_bounds__(NTHR, 2)
k_fused(const float* __restrict__ Lz, const float* __restrict__ Lr,
        const float* __restrict__ Lh, const float* __restrict__ hw,
        const float* __restrict__ hb, float* __restrict__ out) {
    extern __shared__ char smraw[];
    FSmem* sm = reinterpret_cast<FSmem*>(smraw);
    int tid = threadIdx.x;
    int nb = blockIdx.x * NB;

    // ---- cooperative load ----
    {
        const float4* src[3] = {
            reinterpret_cast<const float4*>(Lz) + 1024,
            reinterpret_cast<const float4*>(Lr) + 1024,
            reinterpret_cast<const float4*>(Lh) + 1024};
        float4* dst = &sm->LB[0][0][0];
        for (int i = tid; i < 3 * 1024; i += NTHR) dst[i] = src[i >> 10][i & 1023];

        const float4* wp4 = reinterpret_cast<const float4*>(g_WP);
        float4* wdst = &sm->WP[0][0][0];
        for (int i = tid; i < 384; i += NTHR) wdst[i] = wp4[i];

        float* bdst = &sm->BP[0][0];
        for (int i = tid; i < 192; i += NTHR) bdst[i] = g_BP[i];

        float4* H4 = reinterpret_cast<float4*>(sm->H);
        for (int i = tid; i < NB * 16; i += NTHR) H4[i] = make_float4(0.f, 0.f, 0.f, 0.f);

        const float4* Ax4 = reinterpret_cast<const float4*>(g_Ax);
        float4* A4 = reinterpret_cast<float4*>(sm->u.A);
        for (int i = tid; i < NB * 24; i += NTHR) {
            int n = i / 24, c = i - n * 24;
            int node = nb + n;
            A4[i] = (node < N_NODES) ? Ax4[node * 24 + c] : make_float4(0.f, 0.f, 0.f, 0.f);
        }
    }
    __syncthreads();

    const int cg = tid & 15;        // column group (4 output cols)
    const int ng = (tid >> 4) * 4;  // first of this thread's 4 nodes
    const unsigned wmask = (tid >= 256) ? 0x0000ffffu : 0xffffffffu;

    float hacc[4][4];
#pragma unroll
    for (int n = 0; n < 4; n++)
#pragma unroll
        for (int c = 0; c < 4; c++) hacc[n][c] = 0.0f;

    for (int t = 0; t < PERIODS; t++) {
        float p = g_probs[t];

        // ---- phase 1: z and r gates ----
        u64 az[4][2], ar[4][2];
        {
            float4 b0 = *reinterpret_cast<const float4*>(&sm->BP[0][4 * cg]);
            float4 b1 = *reinterpret_cast<const float4*>(&sm->BP[1][4 * cg]);
#pragma unroll
            for (int n = 0; n < 4; n++) {
                az[n][0] = pack2(b0.x, b0.y); az[n][1] = pack2(b0.z, b0.w);
                ar[n][0] = pack2(b1.x, b1.y); ar[n][1] = pack2(b1.z, b1.w);
            }
        }
#pragma unroll
        for (int f = 0; f < FEAT; f++) {
            ulonglong2 wz = *reinterpret_cast<const ulonglong2*>(&sm->WP[0][f][cg]);
            ulonglong2 wr = *reinterpret_cast<const ulonglong2*>(&sm->WP[1][f][cg]);
#pragma unroll
            for (int n = 0; n < 4; n++) {
                u64 s = packdup(sm->u.A[ng + n][t * 8 + f]);
                az[n][0] = fma2(s, wz.x, az[n][0]); az[n][1] = fma2(s, wz.y, az[n][1]);
                ar[n][0] = fma2(s, wr.x, ar[n][0]); ar[n][1] = fma2(s, wr.y, ar[n][1]);
            }
        }
        for (int k0 = 0; k0 < OUT; k0 += 4) {
            float hv[4][4];
#pragma unroll
            for (int n = 0; n < 4; n++) {
                float4 h4 = *reinterpret_cast<const float4*>(&sm->H[ng + n][k0]);
                hv[n][0] = h4.x; hv[n][1] = h4.y; hv[n][2] = h4.z; hv[n][3] = h4.w;
            }
#pragma unroll
            for (int kk = 0; kk < 4; kk++) {
                ulonglong2 wz = *reinterpret_cast<const ulonglong2*>(&sm->LB[0][k0 + kk][cg]);
                ulonglong2 wr = *reinterpret_cast<const ulonglong2*>(&sm->LB[1][k0 + kk][cg]);
#pragma unroll
                for (int n = 0; n < 4; n++) {
                    u64 s = packdup(hv[n][kk]);
                    az[n][0] = fma2(s, wz.x, az[n][0]); az[n][1] = fma2(s, wz.y, az[n][1]);
                    ar[n][0] = fma2(s, wr.x, ar[n][0]); ar[n][1] = fma2(s, wr.y, ar[n][1]);
                }
            }
        }

        float zf[4][4], holdv[4][4];
#pragma unroll
        for (int n = 0; n < 4; n++) {
            float v0, v1, v2, v3;
            unpack2(az[n][0], v0, v1); unpack2(az[n][1], v2, v3);
            zf[n][0] = sigf(v0); zf[n][1] = sigf(v1); zf[n][2] = sigf(v2); zf[n][3] = sigf(v3);
            float4 hd = *reinterpret_cast<const float4*>(&sm->H[ng + n][4 * cg]);
            holdv[n][0] = hd.x; holdv[n][1] = hd.y; holdv[n][2] = hd.z; holdv[n][3] = hd.w;
        }
        __syncwarp(wmask);   // S1: phase-1 reads of H done
#pragma unroll
        for (int n = 0; n < 4; n++) {
            float v0, v1, v2, v3;
            unpack2(ar[n][0], v0, v1); unpack2(ar[n][1], v2, v3);
            float4 hr;
            hr.x = sigf(v0) * holdv[n][0];
            hr.y = sigf(v1) * holdv[n][1];
            hr.z = sigf(v2) * holdv[n][2];
            hr.w = sigf(v3) * holdv[n][3];
            *reinterpret_cast<float4*>(&sm->H[ng + n][4 * cg]) = hr;   // H := H*R
        }
        __syncwarp(wmask);   // S2: HR visible

        // ---- phase 2: h gate ----
        u64 ah[4][2];
        {
            float4 b2 = *reinterpret_cast<const float4*>(&sm->BP[2][4 * cg]);
#pragma unroll
            for (int n = 0; n < 4; n++) {
                ah[n][0] = pack2(b2.x, b2.y); ah[n][1] = pack2(b2.z, b2.w);
            }
        }
#pragma unroll
        for (int f = 0; f < FEAT; f++) {
            ulonglong2 wh = *reinterpret_cast<const ulonglong2*>(&sm->WP[2][f][cg]);
#pragma unroll
            for (int n = 0; n < 4; n++) {
                u64 s = packdup(sm->u.A[ng + n][t * 8 + f]);
                ah[n][0] = fma2(s, wh.x, ah[n][0]); ah[n][1] = fma2(s, wh.y, ah[n][1]);
            }
        }
        for (int k0 = 0; k0 < OUT; k0 += 4) {
            float hv[4][4];
#pragma unroll
            for (int n = 0; n < 4; n++) {
                float4 h4 = *reinterpret_cast<const float4*>(&sm->H[ng + n][k0]);
                hv[n][0] = h4.x; hv[n][1] = h4.y; hv[n][2] = h4.z; hv[n][3] = h4.w;
            }
#pragma unroll
            for (int kk = 0; kk < 4; kk++) {
                ulonglong2 wh = *reinterpret_cast<const ulonglong2*>(&sm->LB[2][k0 + kk][cg]);
#pragma unroll
                for (int n = 0; n < 4; n++) {
                    u64 s = packdup(hv[n][kk]);
                    ah[n][0] = fma2(s, wh.x, ah[n][0]); ah[n][1] = fma2(s, wh.y, ah[n][1]);
                }
            }
        }

        float hnv[4][4];
#pragma unroll
        for (int n = 0; n < 4; n++) {
            float v0, v1, v2, v3;
            unpack2(ah[n][0], v0, v1); unpack2(ah[n][1], v2, v3);
            float ht[4] = {tanhfast(v0), tanhfast(v1), tanhfast(v2), tanhfast(v3)};
#pragma unroll
            for (int c = 0; c < 4; c++) {
                float hn = zf[n][c] * holdv[n][c] + (1.0f - zf[n][c]) * ht[c];
                hnv[n][c] = hn;
                hacc[n][c] = fmaf(p, hn, hacc[n][c]);
            }
        }
        __syncwarp(wmask);   // S3: phase-2 reads done
#pragma unroll
        for (int n = 0; n < 4; n++) {
            *reinterpret_cast<float4*>(&sm->H[ng + n][4 * cg]) =
                make_float4(hnv[n][0], hnv[n][1], hnv[n][2], hnv[n][3]);
        }
        __syncwarp(wmask);   // S4: new H visible
    }

    // ---- fused head: out = relu(Hacc) @ head_W + head_b ----
    __syncthreads();   // CRITICAL: all warps done reading u.A before Hs overwrites it

#pragma unroll
    for (int n = 0; n < 4; n++)
#pragma unroll
        for (int c = 0; c < 4; c++)
            sm->u.Hs[ng + n][4 * cg + c] = fmaxf(hacc[n][c], 0.0f);

    __syncthreads();   // Hs visible; all done with WP/BP before overwrite

    float* sW = &sm->WP[0][0][0].x;   // reuse: 768 floats
    float* sB = &sm->BP[0][0];
    for (int i = tid; i < OUT * PERIODS; i += NTHR) sW[i] = hw[i];
    if (tid < PERIODS) sB[tid] = hb[tid];
    __syncthreads();

    for (int i = tid; i < NB * PERIODS; i += NTHR) {
        int nn = i / PERIODS;
        int pp = i - nn * PERIODS;
        int node = nb + nn;
        if (node < N_NODES) {
            float acc = sB[pp];
#pragma unroll 16
            for (int o = 0; o < OUT; o++)
                acc = fmaf(sm->u.Hs[nn][o], sW[o * PERIODS + pp], acc);
            out[node * PERIODS + pp] = acc;
        }
    }
}

// ---------------- launch ----------------
extern "C" void kernel_launch(void* const* d_in, const int* in_sizes, int n_in,
                              void* d_out, int out_size) {
    const float* x    = (const float*)d_in[0];
    const int*   ei   = (const int*)d_in[1];
    const float* Wz   = (const float*)d_in[2];
    const float* bz   = (const float*)d_in[3];
    const float* LzW  = (const float*)d_in[4];
    const float* Lzb  = (const float*)d_in[5];
    const float* Wr   = (const float*)d_in[6];
    const float* br   = (const float*)d_in[7];
    const float* LrW  = (const float*)d_in[8];
    const float* Lrb  = (const float*)d_in[9];
    const float* Wh   = (const float*)d_in[10];
    const float* bh   = (const float*)d_in[11];
    const float* LhW  = (const float*)d_in[12];
    const float* Lhb  = (const float*)d_in[13];
    const float* att  = (const float*)d_in[14];
    const float* hW   = (const float*)d_in[15];
    const float* hb   = (const float*)d_in[16];
    float* out = (float*)d_out;

    cudaFuncSetAttribute(k_fused, cudaFuncAttributeMaxDynamicSharedMemorySize,
                         (int)sizeof(FSmem));

    k_zero<<<(N_NODES + 255) / 256, 256>>>();
    k_fill<<<(N_EDGES + 255) / 256, 256>>>(ei);
    k_pre<<<1, 256>>>(Wz, bz, LzW, Lzb, Wr, br, LrW, Lrb, Wh, bh, LhW, Lhb, att);
    k_scale<<<(N_NODES * XDIM + 255) / 256, 256>>>(x);
    k_gather<<<(N_NODES * 32 + 255) / 256, 256>>>();

    k_fused<<<(N_NODES + NB - 1) / NB, NTHR, sizeof(FSmem)>>>(LzW, LrW, LhW, hW, hb, out);
}

// round 10
// speedup vs baseline: 1.5913x; 1.5900x over previous
#include <cuda_runtime.h>
#include <cstdint>

#define N_NODES 20000
#define N_EDGES 640000
#define FEAT 8
#define OUT 64
#define PERIODS 12
#define XDIM 96
#define CAP 128
#define MB2 160
#define THR 320
#define XS 84   // X smem row stride (floats), conflict-free for A frags
#define WS 76   // W smem row stride (floats), conflict-free for B frags

typedef unsigned long long u64;
typedef unsigned int u32;

__device__ __align__(16) int   g_cursor[N_NODES];
__device__ __align__(16) int   g_srcs[N_NODES * CAP];
__device__ __align__(16) float g_xs[N_NODES * XDIM];
__device__ __align__(16) float g_Ax[N_NODES * XDIM];
__device__ __align__(16) float g_WP[3 * FEAT * OUT];
__device__ __align__(16) float g_BP[3 * OUT];
__device__ float g_probs[PERIODS];

__device__ __forceinline__ float sigf(float v) { return __fdividef(1.0f, 1.0f + __expf(-v)); }
__device__ __forceinline__ float tanhfast(float v) {
    return 2.0f * __fdividef(1.0f, 1.0f + __expf(-2.0f * v)) - 1.0f;
}
__device__ __forceinline__ float rna_tf32(float v) {
    float r; asm("cvt.rna.tf32.f32 %0, %1;" : "=f"(r) : "f"(v)); return r;
}
__device__ __forceinline__ void mma8(float* d, u32 a0, u32 a1, u32 a2, u32 a3,
                                     u32 b0, u32 b1) {
    asm volatile("mma.sync.aligned.m16n8k8.row.col.f32.tf32.tf32.f32 "
        "{%0,%1,%2,%3}, {%4,%5,%6,%7}, {%8,%9}, {%0,%1,%2,%3};"
        : "+f"(d[0]), "+f"(d[1]), "+f"(d[2]), "+f"(d[3])
        : "r"(a0), "r"(a1), "r"(a2), "r"(a3), "r"(b0), "r"(b1));
}

// ---- pre kernels (proven) ----
__global__ void k_zero() {
    int i = blockIdx.x * blockDim.x + threadIdx.x;
    if (i < N_NODES) g_cursor[i] = 0;
}
__global__ void k_fill(const int* __restrict__ ei) {
    int e = blockIdx.x * blockDim.x + threadIdx.x;
    if (e >= N_EDGES) return;
    int s = ei[e], d = ei[N_EDGES + e];
    int pos = atomicAdd(&g_cursor[d], 1);
    if (pos < CAP) g_srcs[d * CAP + pos] = s;
}
__global__ void k_scale(const float* __restrict__ x) {
    int idx = blockIdx.x * blockDim.x + threadIdx.x;
    if (idx >= N_NODES * XDIM) return;
    int node = idx / XDIM, r = idx - node * XDIM, t = r >> 3, f = r & 7;
    g_xs[idx] = x[node * XDIM + f * PERIODS + t] * rsqrtf((float)g_cursor[node] + 1.0f);
}
__global__ void __launch_bounds__(256) k_gather() {
    int gw = (blockIdx.x * 256 + threadIdx.x) >> 5;
    if (gw >= N_NODES) return;
    int lane = threadIdx.x & 31, node = gw;
    int deg = g_cursor[node], ndeg = min(deg, CAP);
    const int* bucket = g_srcs + node * CAP;
    float a0 = 0.f, a1 = 0.f, a2 = 0.f;
    for (int j0 = 0; j0 < ndeg; j0 += 32) {
        int sj = (j0 + lane < ndeg) ? bucket[j0 + lane] : 0;
        int lim = min(32, ndeg - j0);
#pragma unroll 4
        for (int jj = 0; jj < lim; jj++) {
            int s = __shfl_sync(0xffffffffu, sj, jj);
            const float* row = g_xs + s * XDIM;
            a0 += row[lane]; a1 += row[lane + 32]; a2 += row[lane + 64];
        }
    }
    const float* self = g_xs + node * XDIM;
    float dd = rsqrtf((float)deg + 1.0f);
    float* dst = g_Ax + node * XDIM;
    dst[lane] = dd * (a0 + self[lane]);
    dst[lane + 32] = dd * (a1 + self[lane + 32]);
    dst[lane + 64] = dd * (a2 + self[lane + 64]);
}
__global__ void k_pre(const float* Wz, const float* bz, const float* Lz, const float* Lzb,
                      const float* Wr, const float* br, const float* Lr, const float* Lrb,
                      const float* Wh, const float* bh, const float* Lh, const float* Lhb,
                      const float* att) {
    const float* W[3] = {Wz, Wr, Wh};
    const float* L[3] = {Lz, Lr, Lh};
    const float* B[3] = {bz, br, bh};
    const float* LB[3] = {Lzb, Lrb, Lhb};
    int tid = threadIdx.x;
    for (int idx = tid; idx < 3 * FEAT * OUT; idx += blockDim.x) {
        int g = idx / (FEAT * OUT), r = idx - g * (FEAT * OUT), f = r / OUT, o = r % OUT;
        float s = 0.0f;
        for (int k = 0; k < OUT; k++) s = fmaf(W[g][f * OUT + k], L[g][k * OUT + o], s);
        g_WP[idx] = s;
    }
    for (int idx = tid; idx < 3 * OUT; idx += blockDim.x) {
        int g = idx / OUT, o = idx % OUT;
        float s = LB[g][o];
        for (int k = 0; k < OUT; k++) s = fmaf(B[g][k], L[g][k * OUT + o], s);
        g_BP[idx] = s;
    }
    if (tid == 0) {
        float m = att[0];
        for (int t = 1; t < PERIODS; t++) m = fmaxf(m, att[t]);
        float e[PERIODS], sum = 0.0f;
        for (int t = 0; t < PERIODS; t++) { e[t] = __expf(att[t] - m); sum += e[t]; }
        float inv = __fdividef(1.0f, sum);
        for (int t = 0; t < PERIODS; t++) g_probs[t] = e[t] * inv;
    }
}

// ---- fused mma.sync kernel ----
struct FS2 {
    float X[MB2][XS];        // cols 0..63 = H, 64..71 = Ax_t (tf32 bits); head reuses as Hs
    float Wt[3][OUT][WS];    // B operand: Wt[g][n][k], k: 0..63 = Lg_bot, 64..71 = WPg
    float BP[3][OUT];
    float probs[PERIODS];
};

__global__ void __launch_bounds__(THR, 1)
k_fused(const float* __restrict__ Lz, const float* __restrict__ Lr,
        const float* __restrict__ Lh, const float* __restrict__ hw,
        const float* __restrict__ hb, float* __restrict__ out) {
    extern __shared__ char smraw[];
    FS2* sm = (FS2*)smraw;
    const int tid = threadIdx.x;
    const int w = tid >> 5, lane = tid & 31;
    const int grp = lane >> 2, tig = lane & 3;
    const int wrow = w * 16;
    const int nb = blockIdx.x * MB2;       // 20000 = 125*160, no bounds checks

    // weights: Wt[g][n][k] = rna_tf32( k<64 ? Lg[(64+k)*64+n] : WP[g][k-64][n] )
    for (int i = tid; i < 3 * OUT * 72; i += THR) {
        int g = i / (OUT * 72), rem = i % (OUT * 72), n = rem / 72, k = rem % 72;
        const float* Lg = (g == 0) ? Lz : (g == 1) ? Lr : Lh;
        float v = (k < 64) ? Lg[(64 + k) * 64 + n] : g_WP[g * 512 + (k - 64) * 64 + n];
        sm->Wt[g][n][k] = rna_tf32(v);
    }
    for (int i = tid; i < 3 * OUT; i += THR) (&sm->BP[0][0])[i] = g_BP[i];
    if (tid < PERIODS) sm->probs[tid] = g_probs[tid];
    for (int i = tid; i < MB2 * OUT; i += THR) sm->X[i >> 6][i & 63] = 0.0f;
    __syncthreads();

    const int row0 = wrow + grp, row1 = row0 + 8;

    float hacc[32];
#pragma unroll
    for (int i = 0; i < 32; i++) hacc[i] = 0.0f;

    for (int t = 0; t < PERIODS; t++) {
        float p = sm->probs[t];

        // stage Ax_t into X cols 64..71 (warp-local rows)
        {
            int arow = wrow + (lane >> 1);
            int acol = (lane & 1) * 4;
            float4 av = *(const float4*)(g_Ax + (nb + arow) * XDIM + t * 8 + acol);
            float4 sv = make_float4(rna_tf32(av.x), rna_tf32(av.y),
                                    rna_tf32(av.z), rna_tf32(av.w));
            *(float4*)&sm->X[arow][64 + acol] = sv;
        }
        __syncwarp();

        // ---- z and r GEMMs ----
        float az[32], ar[32];
#pragma unroll
        for (int i = 0; i < 32; i++) { az[i] = 0.0f; ar[i] = 0.0f; }
#pragma unroll
        for (int kb = 0; kb < 9; kb++) {
            int k0 = kb * 8 + tig;
            u32 a0 = __float_as_uint(sm->X[row0][k0]);
            u32 a1 = __float_as_uint(sm->X[row1][k0]);
            u32 a2 = __float_as_uint(sm->X[row0][k0 + 4]);
            u32 a3 = __float_as_uint(sm->X[row1][k0 + 4]);
#pragma unroll
            for (int nt = 0; nt < 8; nt++) {
                int nrow = nt * 8 + grp;
                u32 bz0 = __float_as_uint(sm->Wt[0][nrow][k0]);
                u32 bz1 = __float_as_uint(sm->Wt[0][nrow][k0 + 4]);
                mma8(az + nt * 4, a0, a1, a2, a3, bz0, bz1);
                u32 br0 = __float_as_uint(sm->Wt[1][nrow][k0]);
                u32 br1 = __float_as_uint(sm->Wt[1][nrow][k0 + 4]);
                mma8(ar + nt * 4, a0, a1, a2, a3, br0, br1);
            }
        }

        // ---- epilogue 1: z=sig, r=sig, H := rna(r*H); az<-zf, ar<-hold ----
#pragma unroll
        for (int nt = 0; nt < 8; nt++) {
            int c0 = nt * 8 + tig * 2;
            float bz0 = sm->BP[0][c0], bz1 = sm->BP[0][c0 + 1];
            float br0 = sm->BP[1][c0], br1 = sm->BP[1][c0 + 1];
            float2 h01 = *(float2*)&sm->X[row0][c0];
            float2 h23 = *(float2*)&sm->X[row1][c0];
            float z0 = sigf(az[nt*4+0] + bz0), z1 = sigf(az[nt*4+1] + bz1);
            float z2 = sigf(az[nt*4+2] + bz0), z3 = sigf(az[nt*4+3] + bz1);
            float r0 = sigf(ar[nt*4+0] + br0), r1 = sigf(ar[nt*4+1] + br1);
            float r2 = sigf(ar[nt*4+2] + br0), r3 = sigf(ar[nt*4+3] + br1);
            float2 hr01 = make_float2(rna_tf32(r0 * h01.x), rna_tf32(r1 * h01.y));
            float2 hr23 = make_float2(rna_tf32(r2 * h23.x), rna_tf32(r3 * h23.y));
            *(float2*)&sm->X[row0][c0] = hr01;
            *(float2*)&sm->X[row1][c0] = hr23;
            az[nt*4+0] = z0; az[nt*4+1] = z1; az[nt*4+2] = z2; az[nt*4+3] = z3;
            ar[nt*4+0] = h01.x; ar[nt*4+1] = h01.y; ar[nt*4+2] = h23.x; ar[nt*4+3] = h23.y;
        }
        __syncwarp();

        // ---- h GEMM ----
        float ah[32];
#pragma unroll
        for (int i = 0; i < 32; i++) ah[i] = 0.0f;
#pragma unroll
        for (int kb = 0; kb < 9; kb++) {
            int k0 = kb * 8 + tig;
            u32 a0 = __float_as_uint(sm->X[row0][k0]);
            u32 a1 = __float_as_uint(sm->X[row1][k0]);
            u32 a2 = __float_as_uint(sm->X[row0][k0 + 4]);
            u32 a3 = __float_as_uint(sm->X[row1][k0 + 4]);
#pragma unroll
            for (int nt = 0; nt < 8; nt++) {
                int nrow = nt * 8 + grp;
                u32 b0 = __float_as_uint(sm->Wt[2][nrow][k0]);
                u32 b1 = __float_as_uint(sm->Wt[2][nrow][k0 + 4]);
                mma8(ah + nt * 4, a0, a1, a2, a3, b0, b1);
            }
        }

        // ---- epilogue 2: Hn = z*hold + (1-z)*tanh(..); hacc += p*Hn ----
#pragma unroll
        for (int nt = 0; nt < 8; nt++) {
            int c0 = nt * 8 + tig * 2;
            float bh0 = sm->BP[2][c0], bh1 = sm->BP[2][c0 + 1];
            float hn[4];
#pragma unroll
            for (int q = 0; q < 4; q++) {
                float bb = (q & 1) ? bh1 : bh0;
                float ht = tanhfast(ah[nt*4+q] + bb);
                float z = az[nt*4+q], hd = ar[nt*4+q];
                float v = z * hd + (1.0f - z) * ht;
                hacc[nt*4+q] = fmaf(p, v, hacc[nt*4+q]);
                hn[q] = rna_tf32(v);
            }
            *(float2*)&sm->X[row0][c0] = make_float2(hn[0], hn[1]);
            *(float2*)&sm->X[row1][c0] = make_float2(hn[2], hn[3]);
        }
        __syncwarp();
    }

    // ---- head: Hs = relu(hacc) in X, then out = Hs @ hw + hb ----
#pragma unroll
    for (int nt = 0; nt < 8; nt++) {
        int c0 = nt * 8 + tig * 2;
        *(float2*)&sm->X[row0][c0] =
            make_float2(fmaxf(hacc[nt*4+0], 0.f), fmaxf(hacc[nt*4+1], 0.f));
        *(float2*)&sm->X[row1][c0] =
            make_float2(fmaxf(hacc[nt*4+2], 0.f), fmaxf(hacc[nt*4+3], 0.f));
    }
    __syncthreads();

    float* sW = &sm->Wt[0][0][0];     // reuse: 768 floats
    float* sB = &sm->BP[0][0];
    for (int i = tid; i < OUT * PERIODS; i += THR) sW[i] = hw[i];
    if (tid < PERIODS) sB[tid] = hb[tid];
    __syncthreads();

    for (int i = tid; i < MB2 * PERIODS; i += THR) {
        int nn = i / PERIODS, pp = i - nn * PERIODS;
        float acc = sB[pp];
#pragma unroll 16
        for (int o = 0; o < OUT; o++)
            acc = fmaf(sm->X[nn][o], sW[o * PERIODS + pp], acc);
        out[(nb + nn) * PERIODS + pp] = acc;
    }
}

extern "C" void kernel_launch(void* const* d_in, const int* in_sizes, int n_in,
                              void* d_out, int out_size) {
    const float* x   = (const float*)d_in[0];
    const int*   ei  = (const int*)d_in[1];
    const float* Wz  = (const float*)d_in[2];
    const float* bz  = (const float*)d_in[3];
    const float* LzW = (const float*)d_in[4];
    const float* Lzb = (const float*)d_in[5];
    const float* Wr  = (const float*)d_in[6];
    const float* br  = (const float*)d_in[7];
    const float* LrW = (const float*)d_in[8];
    const float* Lrb = (const float*)d_in[9];
    const float* Wh  = (const float*)d_in[10];
    const float* bh  = (const float*)d_in[11];
    const float* LhW = (const float*)d_in[12];
    const float* Lhb = (const float*)d_in[13];
    const float* att = (const float*)d_in[14];
    const float* hW  = (const float*)d_in[15];
    const float* hb  = (const float*)d_in[16];
    float* out = (float*)d_out;

    cudaFuncSetAttribute(k_fused, cudaFuncAttributeMaxDynamicSharedMemorySize, (int)sizeof(FS2));

    k_zero<<<(N_NODES + 255) / 256, 256>>>();
    k_fill<<<(N_EDGES + 255) / 256, 256>>>(ei);
    k_pre<<<1, 256>>>(Wz, bz, LzW, Lzb, Wr, br, LrW, Lrb, Wh, bh, LhW, Lhb, att);
    k_scale<<<(N_NODES * XDIM + 255) / 256, 256>>>(x);
    k_gather<<<(N_NODES * 32 + 255) / 256, 256>>>();
    k_fused<<<N_NODES / MB2, THR, sizeof(FS2)>>>(LzW, LrW, LhW, hW, hb, out);
}

// round 12
// speedup vs baseline: 1.6705x; 1.0498x over previous
#include <cuda_runtime.h>
#include <cstdint>

#define N_NODES 20000
#define N_EDGES 640000
#define FEAT 8
#define OUT 64
#define PERIODS 12
#define XDIM 96
#define CAP 128
#define MB2 144
#define THR 288
#define XS 84   // X smem row stride (floats)

typedef unsigned long long u64;
typedef unsigned int u32;

__device__ __align__(16) int   g_cursor[N_NODES];
__device__ __align__(16) int   g_srcs[N_NODES * CAP];
__device__ __align__(16) float g_xs[N_NODES * XDIM];
__device__ __align__(16) float g_Ax[N_NODES * XDIM];
__device__ __align__(16) float g_WP[3 * FEAT * OUT];
__device__ __align__(16) float g_BP[3 * OUT];
__device__ float g_probs[PERIODS];

__device__ __forceinline__ float sigf(float v) { return __fdividef(1.0f, 1.0f + __expf(-v)); }
__device__ __forceinline__ float tanhfast(float v) {
    return 2.0f * __fdividef(1.0f, 1.0f + __expf(-2.0f * v)) - 1.0f;
}
__device__ __forceinline__ float rna_tf32(float v) {
    float r; asm("cvt.rna.tf32.f32 %0, %1;" : "=f"(r) : "f"(v)); return r;
}
__device__ __forceinline__ void mma8(float* d, u32 a0, u32 a1, u32 a2, u32 a3,
                                     u32 b0, u32 b1) {
    asm volatile("mma.sync.aligned.m16n8k8.row.col.f32.tf32.tf32.f32 "
        "{%0,%1,%2,%3}, {%4,%5,%6,%7}, {%8,%9}, {%0,%1,%2,%3};"
        : "+f"(d[0]), "+f"(d[1]), "+f"(d[2]), "+f"(d[3])
        : "r"(a0), "r"(a1), "r"(a2), "r"(a3), "r"(b0), "r"(b1));
}

// ---- K1: zero cursors + fold weights (merged) ----
__global__ void k_init(const float* Wz, const float* bz, const float* Lz, const float* Lzb,
                       const float* Wr, const float* br, const float* Lr, const float* Lrb,
                       const float* Wh, const float* bh, const float* Lh, const float* Lhb,
                       const float* att) {
    int i = blockIdx.x * blockDim.x + threadIdx.x;
    if (i < N_NODES) g_cursor[i] = 0;
    if (blockIdx.x == 0) {
        const float* W[3] = {Wz, Wr, Wh};
        const float* L[3] = {Lz, Lr, Lh};
        const float* B[3] = {bz, br, bh};
        const float* LB[3] = {Lzb, Lrb, Lhb};
        int tid = threadIdx.x;
        for (int idx = tid; idx < 3 * FEAT * OUT; idx += blockDim.x) {
            int g = idx / (FEAT * OUT), r = idx - g * (FEAT * OUT), f = r / OUT, o = r % OUT;
            float s = 0.0f;
            for (int k = 0; k < OUT; k++) s = fmaf(W[g][f * OUT + k], L[g][k * OUT + o], s);
            g_WP[idx] = s;
        }
        for (int idx = tid; idx < 3 * OUT; idx += blockDim.x) {
            int g = idx / OUT, o = idx % OUT;
            float s = LB[g][o];
            for (int k = 0; k < OUT; k++) s = fmaf(B[g][k], L[g][k * OUT + o], s);
            g_BP[idx] = s;
        }
        if (tid == 0) {
            float m = att[0];
            for (int t = 1; t < PERIODS; t++) m = fmaxf(m, att[t]);
            float e[PERIODS], sum = 0.0f;
            for (int t = 0; t < PERIODS; t++) { e[t] = __expf(att[t] - m); sum += e[t]; }
            float inv = __fdividef(1.0f, sum);
            for (int t = 0; t < PERIODS; t++) g_probs[t] = e[t] * inv;
        }
    }
}
__global__ void k_fill(const int* __restrict__ ei) {
    int e = blockIdx.x * blockDim.x + threadIdx.x;
    if (e >= N_EDGES) return;
    int s = ei[e], d = ei[N_EDGES + e];
    int pos = atomicAdd(&g_cursor[d], 1);
    if (pos < CAP) g_srcs[d * CAP + pos] = s;
}
__global__ void k_scale(const float* __restrict__ x) {
    int idx = blockIdx.x * blockDim.x + threadIdx.x;
    if (idx >= N_NODES * XDIM) return;
    int node = idx / XDIM, r = idx - node * XDIM, t = r >> 3, f = r & 7;
    g_xs[idx] = x[node * XDIM + f * PERIODS + t] * rsqrtf((float)g_cursor[node] + 1.0f);
}
__global__ void __launch_bounds__(256) k_gather() {
    int gw = (blockIdx.x * 256 + threadIdx.x) >> 5;
    if (gw >= N_NODES) return;
    int lane = threadIdx.x & 31, node = gw;
    int deg = g_cursor[node], ndeg = min(deg, CAP);
    const int* bucket = g_srcs + node * CAP;
    float a0 = 0.f, a1 = 0.f, a2 = 0.f;
    for (int j0 = 0; j0 < ndeg; j0 += 32) {
        int sj = (j0 + lane < ndeg) ? bucket[j0 + lane] : 0;
        int lim = min(32, ndeg - j0);
#pragma unroll 4
        for (int jj = 0; jj < lim; jj++) {
            int s = __shfl_sync(0xffffffffu, sj, jj);
            const float* row = g_xs + s * XDIM;
            a0 += row[lane]; a1 += row[lane + 32]; a2 += row[lane + 64];
        }
    }
    const float* self = g_xs + node * XDIM;
    float dd = rsqrtf((float)deg + 1.0f);
    float* dst = g_Ax + node * XDIM;
    dst[lane] = dd * (a0 + self[lane]);
    dst[lane + 32] = dd * (a1 + self[lane + 32]);
    dst[lane + 64] = dd * (a2 + self[lane + 64]);
}

// ---- fused mma.sync kernel with pre-packed B fragments ----
struct FS2 {
    float  X[MB2][XS];           // cols 0..63 H, 64..71 Ax_t; head reuses as Hs
    float4 WZR[9][8][32];        // packed z/r B frags: (zb0,zb1,rb0,rb1)  36 KB
    float2 WH[9][8][32];         // packed h B frags                       18 KB
    float  BP[3][OUT];
    float  probs[PERIODS];
};

// gate weight element: k<64 -> Lg_bot[k][n], else WP[g][k-64][n]
__device__ __forceinline__ float welem(const float* Lg, int g, int n, int k) {
    return (k < 64) ? Lg[(64 + k) * 64 + n] : g_WP[g * 512 + (k - 64) * 64 + n];
}

__global__ void __launch_bounds__(THR, 1)
k_fused(const float* __restrict__ Lz, const float* __restrict__ Lr,
        const float* __restrict__ Lh, const float* __restrict__ hw,
        const float* __restrict__ hb, float* __restrict__ out) {
    extern __shared__ char smraw[];
    FS2* sm = (FS2*)smraw;
    const int tid = threadIdx.x;
    const int w = tid >> 5, lane = tid & 31;
    const int grp = lane >> 2, tig = lane & 3;
    const int wrow = w * 16;
    const int nb = blockIdx.x * MB2;

    // pack weight fragments
    for (int i = tid; i < 9 * 8 * 32; i += THR) {
        int kb = i / 256, rem = i & 255, nt = rem >> 5, ln = rem & 31;
        int g2 = ln >> 2, t2 = ln & 3;
        int k0 = kb * 8 + t2, nrow = nt * 8 + g2;
        float4 zr;
        zr.x = rna_tf32(welem(Lz, 0, nrow, k0));
        zr.y = rna_tf32(welem(Lz, 0, nrow, k0 + 4));
        zr.z = rna_tf32(welem(Lr, 1, nrow, k0));
        zr.w = rna_tf32(welem(Lr, 1, nrow, k0 + 4));
        sm->WZR[kb][nt][ln] = zr;
        sm->WH[kb][nt][ln] = make_float2(rna_tf32(welem(Lh, 2, nrow, k0)),
                                         rna_tf32(welem(Lh, 2, nrow, k0 + 4)));
    }
    for (int i = tid; i < 3 * OUT; i += THR) (&sm->BP[0][0])[i] = g_BP[i];
    if (tid < PERIODS) sm->probs[tid] = g_probs[tid];
    for (int i = tid; i < MB2 * OUT; i += THR) sm->X[i >> 6][i & 63] = 0.0f;
    __syncthreads();

    const int row0 = wrow + grp, row1 = row0 + 8;
    const int arow = wrow + (lane >> 1);
    const int anode = nb + arow;
    const bool aok = (anode < N_NODES);

    float hacc[32];
#pragma unroll
    for (int i = 0; i < 32; i++) hacc[i] = 0.0f;

    for (int t = 0; t < PERIODS; t++) {
        float p = sm->probs[t];

        // stage Ax_t into X cols 64..71
        {
            int acol = (lane & 1) * 4;
            float4 av = make_float4(0.f, 0.f, 0.f, 0.f);
            if (aok) av = *(const float4*)(g_Ax + anode * XDIM + t * 8 + acol);
            *(float4*)&sm->X[arow][64 + acol] =
                make_float4(rna_tf32(av.x), rna_tf32(av.y), rna_tf32(av.z), rna_tf32(av.w));
        }
        __syncwarp();

        // ---- z and r GEMMs ----
        float az[32], ar[32];
#pragma unroll
        for (int i = 0; i < 32; i++) { az[i] = 0.0f; ar[i] = 0.0f; }
#pragma unroll
        for (int kb = 0; kb < 9; kb++) {
            int k0 = kb * 8 + tig;
            u32 a0 = __float_as_uint(sm->X[row0][k0]);
            u32 a1 = __float_as_uint(sm->X[row1][k0]);
            u32 a2 = __float_as_uint(sm->X[row0][k0 + 4]);
            u32 a3 = __float_as_uint(sm->X[row1][k0 + 4]);
#pragma unroll
            for (int nt = 0; nt < 8; nt++) {
                float4 b = sm->WZR[kb][nt][lane];
                mma8(az + nt * 4, a0, a1, a2, a3, __float_as_uint(b.x), __float_as_uint(b.y));
                mma8(ar + nt * 4, a0, a1, a2, a3, __float_as_uint(b.z), __float_as_uint(b.w));
            }
        }

        // ---- epilogue 1 ----
#pragma unroll
        for (int nt = 0; nt < 8; nt++) {
            int c0 = nt * 8 + tig * 2;
            float bz0 = sm->BP[0][c0], bz1 = sm->BP[0][c0 + 1];
            float br0 = sm->BP[1][c0], br1 = sm->BP[1][c0 + 1];
            float2 h01 = *(float2*)&sm->X[row0][c0];
            float2 h23 = *(float2*)&sm->X[row1][c0];
            float z0 = sigf(az[nt*4+0] + bz0), z1 = sigf(az[nt*4+1] + bz1);
            float z2 = sigf(az[nt*4+2] + bz0), z3 = sigf(az[nt*4+3] + bz1);
            float r0 = sigf(ar[nt*4+0] + br0), r1 = sigf(ar[nt*4+1] + br1);
            float r2 = sigf(ar[nt*4+2] + br0), r3 = sigf(ar[nt*4+3] + br1);
            *(float2*)&sm->X[row0][c0] = make_float2(rna_tf32(r0 * h01.x), rna_tf32(r1 * h01.y));
            *(float2*)&sm->X[row1][c0] = make_float2(rna_tf32(r2 * h23.x), rna_tf32(r3 * h23.y));
            az[nt*4+0] = z0; az[nt*4+1] = z1; az[nt*4+2] = z2; az[nt*4+3] = z3;
            ar[nt*4+0] = h01.x; ar[nt*4+1] = h01.y; ar[nt*4+2] = h23.x; ar[nt*4+3] = h23.y;
        }
        __syncwarp();

        // ---- h GEMM ----
        float ah[32];
#pragma unroll
        for (int i = 0; i < 32; i++) ah[i] = 0.0f;
#pragma unroll
        for (int kb = 0; kb < 9; kb++) {
            int k0 = kb * 8 + tig;
            u32 a0 = __float_as_uint(sm->X[row0][k0]);
            u32 a1 = __float_as_uint(sm->X[row1][k0]);
            u32 a2 = __float_as_uint(sm->X[row0][k0 + 4]);
            u32 a3 = __float_as_uint(sm->X[row1][k0 + 4]);
#pragma unroll
            for (int nt = 0; nt < 8; nt++) {
                float2 b = sm->WH[kb][nt][lane];
                mma8(ah + nt * 4, a0, a1, a2, a3, __float_as_uint(b.x), __float_as_uint(b.y));
            }
        }

        // ---- epilogue 2 ----
#pragma unroll
        for (int nt = 0; nt < 8; nt++) {
            int c0 = nt * 8 + tig * 2;
            float bh0 = sm->BP[2][c0], bh1 = sm->BP[2][c0 + 1];
            float hn[4];
#pragma unroll
            for (int q = 0; q < 4; q++) {
                float bb = (q & 1) ? bh1 : bh0;
                float ht = tanhfast(ah[nt*4+q] + bb);
                float z = az[nt*4+q], hd = ar[nt*4+q];
                float v = z * hd + (1.0f - z) * ht;
                hacc[nt*4+q] = fmaf(p, v, hacc[nt*4+q]);
                hn[q] = rna_tf32(v);
            }
            *(float2*)&sm->X[row0][c0] = make_float2(hn[0], hn[1]);
            *(float2*)&sm->X[row1][c0] = make_float2(hn[2], hn[3]);
        }
        __syncwarp();
    }

    // ---- head ----
#pragma unroll
    for (int nt = 0; nt < 8; nt++) {
        int c0 = nt * 8 + tig * 2;
        *(float2*)&sm->X[row0][c0] =
            make_float2(fmaxf(hacc[nt*4+0], 0.f), fmaxf(hacc[nt*4+1], 0.f));
        *(float2*)&sm->X[row1][c0] =
            make_float2(fmaxf(hacc[nt*4+2], 0.f), fmaxf(hacc[nt*4+3], 0.f));
    }
    __syncthreads();

    float* sW = (float*)&sm->WZR[0][0][0];   // reuse: 768 floats
    float* sB = &sm->BP[0][0];
    for (int i = tid; i < OUT * PERIODS; i += THR) sW[i] = hw[i];
    if (tid < PERIODS) sB[tid] = hb[tid];
    __syncthreads();

    for (int i = tid; i < MB2 * PERIODS; i += THR) {
        int nn = i / PERIODS, pp = i - nn * PERIODS;
        int node = nb + nn;
        if (node >= N_NODES) continue;
        float acc = sB[pp];
#pragma unroll 16
        for (int o = 0; o < OUT; o++)
            acc = fmaf(sm->X[nn][o], sW[o * PERIODS + pp], acc);
        out[node * PERIODS + pp] = acc;
    }
}

extern "C" void kernel_launch(void* const* d_in, const int* in_sizes, int n_in,
                              void* d_out, int out_size) {
    const float* x   = (const float*)d_in[0];
    const int*   ei  = (const int*)d_in[1];
    const float* Wz  = (const float*)d_in[2];
    const float* bz  = (const float*)d_in[3];
    const float* LzW = (const float*)d_in[4];
    const float* Lzb = (const float*)d_in[5];
    const float* Wr  = (const float*)d_in[6];
    const float* br  = (const float*)d_in[7];
    const float* LrW = (const float*)d_in[8];
    const float* Lrb = (const float*)d_in[9];
    const float* Wh  = (const float*)d_in[10];
    const float* bh  = (const float*)d_in[11];
    const float* LhW = (const float*)d_in[12];
    const float* Lhb = (const float*)d_in[13];
    const float* att = (const float*)d_in[14];
    const float* hW  = (const float*)d_in[15];
    const float* hb  = (const float*)d_in[16];
    float* out = (float*)d_out;

    cudaFuncSetAttribute(k_fused, cudaFuncAttributeMaxDynamicSharedMemorySize, (int)sizeof(FS2));

    k_init<<<(N_NODES + 255) / 256, 256>>>(Wz, bz, LzW, Lzb, Wr, br, LrW, Lrb,
                                           Wh, bh, LhW, Lhb, att);
    k_fill<<<(N_EDGES + 255) / 256, 256>>>(ei);
    k_scale<<<(N_NODES * XDIM + 255) / 256, 256>>>(x);
    k_gather<<<(N_NODES * 32 + 255) / 256, 256>>>();
    k_fused<<<(N_NODES + MB2 - 1) / MB2, THR, sizeof(FS2)>>>(LzW, LrW, LhW, hW, hb, out);
}

// round 13
// speedup vs baseline: 1.7807x; 1.0659x over previous
#include <cuda_runtime.h>
#include <cstdint>

#define N_NODES 20000
#define N_EDGES 640000
#define FEAT 8
#define OUT 64
#define PERIODS 12
#define XDIM 96
#define CAP 128
#define MB2 144
#define THR 288
#define XS 84   // X smem row stride (floats)

typedef unsigned long long u64;
typedef unsigned int u32;

__device__ __align__(16) int   g_cursor[N_NODES];
__device__ __align__(16) int   g_srcs[N_NODES * CAP];
__device__ __align__(16) float g_Ax[N_NODES * XDIM];   // t-major rows
__device__ __align__(16) float g_WP[3 * FEAT * OUT];
__device__ __align__(16) float g_BP[3 * OUT];
__device__ float g_probs[PERIODS];

__device__ __forceinline__ float tanha(float v) {
    float r; asm("tanh.approx.f32 %0, %1;" : "=f"(r) : "f"(v)); return r;
}
__device__ __forceinline__ float sigf(float v) { return fmaf(0.5f, tanha(0.5f * v), 0.5f); }
__device__ __forceinline__ float rna_tf32(float v) {
    float r; asm("cvt.rna.tf32.f32 %0, %1;" : "=f"(r) : "f"(v)); return r;
}
__device__ __forceinline__ void mma8(float* d, u32 a0, u32 a1, u32 a2, u32 a3,
                                     u32 b0, u32 b1) {
    asm volatile("mma.sync.aligned.m16n8k8.row.col.f32.tf32.tf32.f32 "
        "{%0,%1,%2,%3}, {%4,%5,%6,%7}, {%8,%9}, {%0,%1,%2,%3};"
        : "+f"(d[0]), "+f"(d[1]), "+f"(d[2]), "+f"(d[3])
        : "r"(a0), "r"(a1), "r"(a2), "r"(a3), "r"(b0), "r"(b1));
}

// ---- K1: zero cursors + fold weights ----
__global__ void k_init(const float* Wz, const float* bz, const float* Lz, const float* Lzb,
                       const float* Wr, const float* br, const float* Lr, const float* Lrb,
                       const float* Wh, const float* bh, const float* Lh, const float* Lhb,
                       const float* att) {
    int i = blockIdx.x * blockDim.x + threadIdx.x;
    if (i < N_NODES) g_cursor[i] = 0;
    if (blockIdx.x == 0) {
        const float* W[3] = {Wz, Wr, Wh};
        const float* L[3] = {Lz, Lr, Lh};
        const float* B[3] = {bz, br, bh};
        const float* LB[3] = {Lzb, Lrb, Lhb};
        int tid = threadIdx.x;
        for (int idx = tid; idx < 3 * FEAT * OUT; idx += blockDim.x) {
            int g = idx / (FEAT * OUT), r = idx - g * (FEAT * OUT), f = r / OUT, o = r % OUT;
            float s = 0.0f;
            for (int k = 0; k < OUT; k++) s = fmaf(W[g][f * OUT + k], L[g][k * OUT + o], s);
            g_WP[idx] = s;
        }
        for (int idx = tid; idx < 3 * OUT; idx += blockDim.x) {
            int g = idx / OUT, o = idx % OUT;
            float s = LB[g][o];
            for (int k = 0; k < OUT; k++) s = fmaf(B[g][k], L[g][k * OUT + o], s);
            g_BP[idx] = s;
        }
        if (tid == 0) {
            float m = att[0];
            for (int t = 1; t < PERIODS; t++) m = fmaxf(m, att[t]);
            float e[PERIODS], sum = 0.0f;
            for (int t = 0; t < PERIODS; t++) { e[t] = __expf(att[t] - m); sum += e[t]; }
            float inv = __fdividef(1.0f, sum);
            for (int t = 0; t < PERIODS; t++) g_probs[t] = e[t] * inv;
        }
    }
}
__global__ void k_fill(const int* __restrict__ ei) {
    int e = blockIdx.x * blockDim.x + threadIdx.x;
    if (e >= N_EDGES) return;
    int s = ei[e], d = ei[N_EDGES + e];
    int pos = atomicAdd(&g_cursor[d], 1);
    if (pos < CAP) g_srcs[d * CAP + pos] = s;
}

// ---- gather: raw x, dinv folded in, transposed write (replaces scale+gather) ----
__global__ void __launch_bounds__(256) k_gather(const float* __restrict__ x) {
    int gw = (blockIdx.x * 256 + threadIdx.x) >> 5;
    if (gw >= N_NODES) return;
    int lane = threadIdx.x & 31, node = gw;
    int deg = g_cursor[node], ndeg = min(deg, CAP);
    const int* bucket = g_srcs + node * CAP;
    float a0 = 0.f, a1 = 0.f, a2 = 0.f;
    for (int j0 = 0; j0 < ndeg; j0 += 32) {
        int idx = j0 + lane;
        int sj = (idx < ndeg) ? bucket[idx] : 0;
        float dv = (idx < ndeg) ? rsqrtf((float)g_cursor[sj] + 1.0f) : 0.0f;
        int lim = min(32, ndeg - j0);
#pragma unroll 4
        for (int jj = 0; jj < lim; jj++) {
            int s = __shfl_sync(0xffffffffu, sj, jj);
            float d = __shfl_sync(0xffffffffu, dv, jj);
            const float* row = x + s * XDIM;
            a0 = fmaf(d, row[lane], a0);
            a1 = fmaf(d, row[lane + 32], a1);
            a2 = fmaf(d, row[lane + 64], a2);
        }
    }
    float dd = rsqrtf((float)deg + 1.0f);
    const float* self = x + node * XDIM;
    float* dst = g_Ax + node * XDIM;
    // f-major col c = f*PERIODS + t  ->  t-major index t*8 + f
    int c0 = lane, c1 = lane + 32, c2 = lane + 64;
    dst[(c0 % PERIODS) * 8 + c0 / PERIODS] = dd * fmaf(dd, self[c0], a0);
    dst[(c1 % PERIODS) * 8 + c1 / PERIODS] = dd * fmaf(dd, self[c1], a1);
    dst[(c2 % PERIODS) * 8 + c2 / PERIODS] = dd * fmaf(dd, self[c2], a2);
}

// ---- fused mma.sync kernel ----
struct FS2 {
    float  X[MB2][XS];           // cols 0..63 H, 64..71 Ax_t; head reuses as Hs
    float4 WZR[9][8][32];        // packed z/r B frags (k-permuted)
    float2 WH[9][8][32];         // packed h B frags (k-permuted)
    float  BP[3][OUT];
    float  probs[PERIODS];
};

__device__ __forceinline__ float welem(const float* Lg, int g, int n, int k) {
    return (k < 64) ? Lg[(64 + k) * 64 + n] : g_WP[g * 512 + (k - 64) * 64 + n];
}

__global__ void __launch_bounds__(THR, 1)
k_fused(const float* __restrict__ Lz, const float* __restrict__ Lr,
        const float* __restrict__ Lh, const float* __restrict__ hw,
        const float* __restrict__ hb, float* __restrict__ out) {
    extern __shared__ char smraw[];
    FS2* sm = (FS2*)smraw;
    const int tid = threadIdx.x;
    const int w = tid >> 5, lane = tid & 31;
    const int grp = lane >> 2, tig = lane & 3;
    const int wrow = w * 16;
    const int nb = blockIdx.x * MB2;

    // pack weight fragments; k-permutation: frag slots (t2, t2+4) <- phys (2*t2, 2*t2+1)
    for (int i = tid; i < 9 * 8 * 32; i += THR) {
        int kb = i / 256, rem = i & 255, nt = rem >> 5, ln = rem & 31;
        int g2 = ln >> 2, t2 = ln & 3;
        int kA = kb * 8 + 2 * t2, kB = kA + 1, nrow = nt * 8 + g2;
        float4 zr;
        zr.x = rna_tf32(welem(Lz, 0, nrow, kA));
        zr.y = rna_tf32(welem(Lz, 0, nrow, kB));
        zr.z = rna_tf32(welem(Lr, 1, nrow, kA));
        zr.w = rna_tf32(welem(Lr, 1, nrow, kB));
        sm->WZR[kb][nt][ln] = zr;
        sm->WH[kb][nt][ln] = make_float2(rna_tf32(welem(Lh, 2, nrow, kA)),
                                         rna_tf32(welem(Lh, 2, nrow, kB)));
    }
    for (int i = tid; i < 3 * OUT; i += THR) (&sm->BP[0][0])[i] = g_BP[i];
    if (tid < PERIODS) sm->probs[tid] = g_probs[tid];
    for (int i = tid; i < MB2 * OUT; i += THR) sm->X[i >> 6][i & 63] = 0.0f;
    __syncthreads();

    const int row0 = wrow + grp, row1 = row0 + 8;
    const int arow = wrow + (lane >> 1);
    const int anode = nb + arow;
    const bool aok = (anode < N_NODES);

    float hacc[32];
#pragma unroll
    for (int i = 0; i < 32; i++) hacc[i] = 0.0f;

    for (int t = 0; t < PERIODS; t++) {
        float p = sm->probs[t];

        // stage Ax_t into X cols 64..71
        {
            int acol = (lane & 1) * 4;
            float4 av = make_float4(0.f, 0.f, 0.f, 0.f);
            if (aok) av = *(const float4*)(g_Ax + anode * XDIM + t * 8 + acol);
            *(float4*)&sm->X[arow][64 + acol] =
                make_float4(rna_tf32(av.x), rna_tf32(av.y), rna_tf32(av.z), rna_tf32(av.w));
        }
        __syncwarp();

        // ---- z and r GEMMs ----
        float az[32], ar[32];
#pragma unroll
        for (int i = 0; i < 32; i++) { az[i] = 0.0f; ar[i] = 0.0f; }
#pragma unroll
        for (int kb = 0; kb < 9; kb++) {
            float2 va = *(float2*)&sm->X[row0][kb * 8 + 2 * tig];
            float2 vb = *(float2*)&sm->X[row1][kb * 8 + 2 * tig];
            u32 a0 = __float_as_uint(va.x), a2 = __float_as_uint(va.y);
            u32 a1 = __float_as_uint(vb.x), a3 = __float_as_uint(vb.y);
#pragma unroll
            for (int nt = 0; nt < 8; nt++) {
                float4 b = sm->WZR[kb][nt][lane];
                mma8(az + nt * 4, a0, a1, a2, a3, __float_as_uint(b.x), __float_as_uint(b.y));
                mma8(ar + nt * 4, a0, a1, a2, a3, __float_as_uint(b.z), __float_as_uint(b.w));
            }
        }

        // ---- epilogue 1 ----
#pragma unroll
        for (int nt = 0; nt < 8; nt++) {
            int c0 = nt * 8 + tig * 2;
            float2 bz = *(float2*)&sm->BP[0][c0];
            float2 br = *(float2*)&sm->BP[1][c0];
            float2 h01 = *(float2*)&sm->X[row0][c0];
            float2 h23 = *(float2*)&sm->X[row1][c0];
            float z0 = sigf(az[nt*4+0] + bz.x), z1 = sigf(az[nt*4+1] + bz.y);
            float z2 = sigf(az[nt*4+2] + bz.x), z3 = sigf(az[nt*4+3] + bz.y);
            float r0 = sigf(ar[nt*4+0] + br.x), r1 = sigf(ar[nt*4+1] + br.y);
            float r2 = sigf(ar[nt*4+2] + br.x), r3 = sigf(ar[nt*4+3] + br.y);
            *(float2*)&sm->X[row0][c0] = make_float2(rna_tf32(r0 * h01.x), rna_tf32(r1 * h01.y));
            *(float2*)&sm->X[row1][c0] = make_float2(rna_tf32(r2 * h23.x), rna_tf32(r3 * h23.y));
            az[nt*4+0] = z0; az[nt*4+1] = z1; az[nt*4+2] = z2; az[nt*4+3] = z3;
            ar[nt*4+0] = h01.x; ar[nt*4+1] = h01.y; ar[nt*4+2] = h23.x; ar[nt*4+3] = h23.y;
        }
        __syncwarp();

        // ---- h GEMM ----
        float ah[32];
#pragma unroll
        for (int i = 0; i < 32; i++) ah[i] = 0.0f;
#pragma unroll
        for (int kb = 0; kb < 9; kb++) {
            float2 va = *(float2*)&sm->X[row0][kb * 8 + 2 * tig];
            float2 vb = *(float2*)&sm->X[row1][kb * 8 + 2 * tig];
            u32 a0 = __float_as_uint(va.x), a2 = __float_as_uint(va.y);
            u32 a1 = __float_as_uint(vb.x), a3 = __float_as_uint(vb.y);
#pragma unroll
            for (int nt = 0; nt < 8; nt++) {
                float2 b = sm->WH[kb][nt][lane];
                mma8(ah + nt * 4, a0, a1, a2, a3, __float_as_uint(b.x), __float_as_uint(b.y));
            }
        }

        // ---- epilogue 2 ----
#pragma unroll
        for (int nt = 0; nt < 8; nt++) {
            int c0 = nt * 8 + tig * 2;
            float2 bh = *(float2*)&sm->BP[2][c0];
            float hn[4];
#pragma unroll
            for (int q = 0; q < 4; q++) {
                float bb = (q & 1) ? bh.y : bh.x;
                float ht = tanha(ah[nt*4+q] + bb);
                float z = az[nt*4+q], hd = ar[nt*4+q];
                float v = z * hd + (1.0f - z) * ht;
                hacc[nt*4+q] = fmaf(p, v, hacc[nt*4+q]);
                hn[q] = rna_tf32(v);
            }
            *(float2*)&sm->X[row0][c0] = make_float2(hn[0], hn[1]);
            *(float2*)&sm->X[row1][c0] = make_float2(hn[2], hn[3]);
        }
        __syncwarp();
    }

    // ---- head ----
#pragma unroll
    for (int nt = 0; nt < 8; nt++) {
        int c0 = nt * 8 + tig * 2;
        *(float2*)&sm->X[row0][c0] =
            make_float2(fmaxf(hacc[nt*4+0], 0.f), fmaxf(hacc[nt*4+1], 0.f));
        *(float2*)&sm->X[row1][c0] =
            make_float2(fmaxf(hacc[nt*4+2], 0.f), fmaxf(hacc[nt*4+3], 0.f));
    }
    __syncthreads();

    float* sW = (float*)&sm->WZR[0][0][0];
    float* sB = &sm->BP[0][0];
    for (int i = tid; i < OUT * PERIODS; i += THR) sW[i] = hw[i];
    if (tid < PERIODS) sB[tid] = hb[tid];
    __syncthreads();

    for (int i = tid; i < MB2 * PERIODS; i += THR) {
        int nn = i / PERIODS, pp = i - nn * PERIODS;
        int node = nb + nn;
        if (node >= N_NODES) continue;
        float acc = sB[pp];
#pragma unroll 16
        for (int o = 0; o < OUT; o++)
            acc = fmaf(sm->X[nn][o], sW[o * PERIODS + pp], acc);
        out[node * PERIODS + pp] = acc;
    }
}

extern "C" void kernel_launch(void* const* d_in, const int* in_sizes, int n_in,
                              void* d_out, int out_size) {
    const float* x   = (const float*)d_in[0];
    const int*   ei  = (const int*)d_in[1];
    const float* Wz  = (const float*)d_in[2];
    const float* bz  = (const float*)d_in[3];
    const float* LzW = (const float*)d_in[4];
    const float* Lzb = (const float*)d_in[5];
    const float* Wr  = (const float*)d_in[6];
    const float* br  = (const float*)d_in[7];
    const float* LrW = (const float*)d_in[8];
    const float* Lrb = (const float*)d_in[9];
    const float* Wh  = (const float*)d_in[10];
    const float* bh  = (const float*)d_in[11];
    const float* LhW = (const float*)d_in[12];
    const float* Lhb = (const float*)d_in[13];
    const float* att = (const float*)d_in[14];
    const float* hW  = (const float*)d_in[15];
    const float* hb  = (const float*)d_in[16];
    float* out = (float*)d_out;

    cudaFuncSetAttribute(k_fused, cudaFuncAttributeMaxDynamicSharedMemorySize, (int)sizeof(FS2));

    k_init<<<(N_NODES + 255) / 256, 256>>>(Wz, bz, LzW, Lzb, Wr, br, LrW, Lrb,
                                           Wh, bh, LhW, Lhb, att);
    k_fill<<<(N_EDGES + 255) / 256, 256>>>(ei);
    k_gather<<<(N_NODES * 32 + 255) / 256, 256>>>(x);
    k_fused<<<(N_NODES + MB2 - 1) / MB2, THR, sizeof(FS2)>>>(LzW, LrW, LhW, hW, hb, out);
}

// round 14
// speedup vs baseline: 1.8586x; 1.0438x over previous
#include <cuda_runtime.h>
#include <cstdint>

#define N_NODES 20000
#define N_EDGES 640000
#define FEAT 8
#define OUT 64
#define PERIODS 12
#define XDIM 96
#define CAP 128
#define MB2 144
#define THR 576
#define XS 84   // X smem row stride (floats)

typedef unsigned long long u64;
typedef unsigned int u32;

__device__ __align__(16) int   g_cursor[N_NODES];
__device__ __align__(16) int   g_srcs[N_NODES * CAP];
__device__ __align__(16) float g_Ax[N_NODES * XDIM];   // t-major rows
__device__ __align__(16) float g_WP[3 * FEAT * OUT];
__device__ __align__(16) float g_BP[3 * OUT];
__device__ float g_probs[PERIODS];

__device__ __forceinline__ float tanha(float v) {
    float r; asm("tanh.approx.f32 %0, %1;" : "=f"(r) : "f"(v)); return r;
}
__device__ __forceinline__ float sigf(float v) { return fmaf(0.5f, tanha(0.5f * v), 0.5f); }
__device__ __forceinline__ float rna_tf32(float v) {
    float r; asm("cvt.rna.tf32.f32 %0, %1;" : "=f"(r) : "f"(v)); return r;
}
__device__ __forceinline__ void mma8(float* d, u32 a0, u32 a1, u32 a2, u32 a3,
                                     u32 b0, u32 b1) {
    asm volatile("mma.sync.aligned.m16n8k8.row.col.f32.tf32.tf32.f32 "
        "{%0,%1,%2,%3}, {%4,%5,%6,%7}, {%8,%9}, {%0,%1,%2,%3};"
        : "+f"(d[0]), "+f"(d[1]), "+f"(d[2]), "+f"(d[3])
        : "r"(a0), "r"(a1), "r"(a2), "r"(a3), "r"(b0), "r"(b1));
}
__device__ __forceinline__ void barpair(int tile) {
    asm volatile("bar.sync %0, %1;" :: "r"(tile + 1), "r"(64) : "memory");
}

// ---- K1: zero cursors + fold weights ----
__global__ void k_init(const float* Wz, const float* bz, const float* Lz, const float* Lzb,
                       const float* Wr, const float* br, const float* Lr, const float* Lrb,
                       const float* Wh, const float* bh, const float* Lh, const float* Lhb,
                       const float* att) {
    int i = blockIdx.x * blockDim.x + threadIdx.x;
    if (i < N_NODES) g_cursor[i] = 0;
    if (blockIdx.x == 0) {
        const float* W[3] = {Wz, Wr, Wh};
        const float* L[3] = {Lz, Lr, Lh};
        const float* B[3] = {bz, br, bh};
        const float* LB[3] = {Lzb, Lrb, Lhb};
        int tid = threadIdx.x;
        for (int idx = tid; idx < 3 * FEAT * OUT; idx += blockDim.x) {
            int g = idx / (FEAT * OUT), r = idx - g * (FEAT * OUT), f = r / OUT, o = r % OUT;
            float s = 0.0f;
            for (int k = 0; k < OUT; k++) s = fmaf(W[g][f * OUT + k], L[g][k * OUT + o], s);
            g_WP[idx] = s;
        }
        for (int idx = tid; idx < 3 * OUT; idx += blockDim.x) {
            int g = idx / OUT, o = idx % OUT;
            float s = LB[g][o];
            for (int k = 0; k < OUT; k++) s = fmaf(B[g][k], L[g][k * OUT + o], s);
            g_BP[idx] = s;
        }
        if (tid == 0) {
            float m = att[0];
            for (int t = 1; t < PERIODS; t++) m = fmaxf(m, att[t]);
            float e[PERIODS], sum = 0.0f;
            for (int t = 0; t < PERIODS; t++) { e[t] = __expf(att[t] - m); sum += e[t]; }
            float inv = __fdividef(1.0f, sum);
            for (int t = 0; t < PERIODS; t++) g_probs[t] = e[t] * inv;
        }
    }
}
__global__ void k_fill(const int* __restrict__ ei) {
    int e = blockIdx.x * blockDim.x + threadIdx.x;
    if (e >= N_EDGES) return;
    int s = ei[e], d = ei[N_EDGES + e];
    int pos = atomicAdd(&g_cursor[d], 1);
    if (pos < CAP) g_srcs[d * CAP + pos] = s;
}

// ---- gather: raw x, dinv folded in, transposed write ----
__global__ void __launch_bounds__(256) k_gather(const float* __restrict__ x) {
    int gw = (blockIdx.x * 256 + threadIdx.x) >> 5;
    if (gw >= N_NODES) return;
    int lane = threadIdx.x & 31, node = gw;
    int deg = g_cursor[node], ndeg = min(deg, CAP);
    const int* bucket = g_srcs + node * CAP;
    float a0 = 0.f, a1 = 0.f, a2 = 0.f;
    for (int j0 = 0; j0 < ndeg; j0 += 32) {
        int idx = j0 + lane;
        int sj = (idx < ndeg) ? bucket[idx] : 0;
        float dv = (idx < ndeg) ? rsqrtf((float)g_cursor[sj] + 1.0f) : 0.0f;
        int lim = min(32, ndeg - j0);
#pragma unroll 4
        for (int jj = 0; jj < lim; jj++) {
            int s = __shfl_sync(0xffffffffu, sj, jj);
            float d = __shfl_sync(0xffffffffu, dv, jj);
            const float* row = x + s * XDIM;
            a0 = fmaf(d, row[lane], a0);
            a1 = fmaf(d, row[lane + 32], a1);
            a2 = fmaf(d, row[lane + 64], a2);
        }
    }
    float dd = rsqrtf((float)deg + 1.0f);
    const float* self = x + node * XDIM;
    float* dst = g_Ax + node * XDIM;
    int c0 = lane, c1 = lane + 32, c2 = lane + 64;
    dst[(c0 % PERIODS) * 8 + c0 / PERIODS] = dd * fmaf(dd, self[c0], a0);
    dst[(c1 % PERIODS) * 8 + c1 / PERIODS] = dd * fmaf(dd, self[c1], a1);
    dst[(c2 % PERIODS) * 8 + c2 / PERIODS] = dd * fmaf(dd, self[c2], a2);
}

// ---- fused mma.sync kernel: 2 warps per 16-row tile (n split 32/32) ----
struct FS2 {
    float  X[MB2][XS];
    float4 WZR[9][8][32];
    float2 WH[9][8][32];
    float  BP[3][OUT];
    float  probs[PERIODS];
};

__device__ __forceinline__ float welem(const float* Lg, int g, int n, int k) {
    return (k < 64) ? Lg[(64 + k) * 64 + n] : g_WP[g * 512 + (k - 64) * 64 + n];
}

__global__ void __launch_bounds__(THR, 1)
k_fused(const float* __restrict__ Lz, const float* __restrict__ Lr,
        const float* __restrict__ Lh, const float* __restrict__ hw,
        const float* __restrict__ hb, float* __restrict__ out) {
    extern __shared__ char smraw[];
    FS2* sm = (FS2*)smraw;
    const int tid = threadIdx.x;
    const int w = tid >> 5, lane = tid & 31;
    const int tile = w >> 1, side = w & 1;
    const int grp = lane >> 2, tig = lane & 3;
    const int wrow = tile * 16;
    const int ntb = side * 4;           // this warp's first n-tile (of 8)
    const int nb = blockIdx.x * MB2;

    // pack weight fragments (k-permuted: slots (t2, t2+4) <- phys (2t2, 2t2+1))
    for (int i = tid; i < 9 * 8 * 32; i += THR) {
        int kb = i / 256, rem = i & 255, nt = rem >> 5, ln = rem & 31;
        int g2 = ln >> 2, t2 = ln & 3;
        int kA = kb * 8 + 2 * t2, kB = kA + 1, nrow = nt * 8 + g2;
        float4 zr;
        zr.x = rna_tf32(welem(Lz, 0, nrow, kA));
        zr.y = rna_tf32(welem(Lz, 0, nrow, kB));
        zr.z = rna_tf32(welem(Lr, 1, nrow, kA));
        zr.w = rna_tf32(welem(Lr, 1, nrow, kB));
        sm->WZR[kb][nt][ln] = zr;
        sm->WH[kb][nt][ln] = make_float2(rna_tf32(welem(Lh, 2, nrow, kA)),
                                         rna_tf32(welem(Lh, 2, nrow, kB)));
    }
    for (int i = tid; i < 3 * OUT; i += THR) (&sm->BP[0][0])[i] = g_BP[i];
    if (tid < PERIODS) sm->probs[tid] = g_probs[tid];
    for (int i = tid; i < MB2 * OUT; i += THR) sm->X[i >> 6][i & 63] = 0.0f;
    __syncthreads();

    const int row0 = wrow + grp, row1 = row0 + 8;
    const int arow = wrow + (lane >> 1);
    const int anode = nb + arow;
    const bool aok = (anode < N_NODES);

    float hacc[16];
#pragma unroll
    for (int i = 0; i < 16; i++) hacc[i] = 0.0f;

    for (int t = 0; t < PERIODS; t++) {
        float p = sm->probs[t];

        // side 0 stages Ax_t into X cols 64..71 for this tile's 16 rows
        if (side == 0) {
            int acol = (lane & 1) * 4;
            float4 av = make_float4(0.f, 0.f, 0.f, 0.f);
            if (aok) av = *(const float4*)(g_Ax + anode * XDIM + t * 8 + acol);
            *(float4*)&sm->X[arow][64 + acol] =
                make_float4(rna_tf32(av.x), rna_tf32(av.y), rna_tf32(av.z), rna_tf32(av.w));
        }
        barpair(tile);   // stage + partner's prev-step epi2 visible

        // ---- z and r GEMMs (this warp: n-tiles ntb..ntb+3) ----
        float az[16], ar[16];
#pragma unroll
        for (int i = 0; i < 16; i++) { az[i] = 0.0f; ar[i] = 0.0f; }
#pragma unroll
        for (int kb = 0; kb < 9; kb++) {
            float2 va = *(float2*)&sm->X[row0][kb * 8 + 2 * tig];
            float2 vb = *(float2*)&sm->X[row1][kb * 8 + 2 * tig];
            u32 a0 = __float_as_uint(va.x), a2 = __float_as_uint(va.y);
            u32 a1 = __float_as_uint(vb.x), a3 = __float_as_uint(vb.y);
#pragma unroll
            for (int nt = 0; nt < 4; nt++) {
                float4 b = sm->WZR[kb][ntb + nt][lane];
                mma8(az + nt * 4, a0, a1, a2, a3, __float_as_uint(b.x), __float_as_uint(b.y));
                mma8(ar + nt * 4, a0, a1, a2, a3, __float_as_uint(b.z), __float_as_uint(b.w));
            }
        }

        // ---- epilogue 1 (own 32 cols) ----
#pragma unroll
        for (int nt = 0; nt < 4; nt++) {
            int c0 = (ntb + nt) * 8 + tig * 2;
            float2 bz = *(float2*)&sm->BP[0][c0];
            float2 br = *(float2*)&sm->BP[1][c0];
            float2 h01 = *(float2*)&sm->X[row0][c0];
            float2 h23 = *(float2*)&sm->X[row1][c0];
            float z0 = sigf(az[nt*4+0] + bz.x), z1 = sigf(az[nt*4+1] + bz.y);
            float z2 = sigf(az[nt*4+2] + bz.x), z3 = sigf(az[nt*4+3] + bz.y);
            float r0 = sigf(ar[nt*4+0] + br.x), r1 = sigf(ar[nt*4+1] + br.y);
            float r2 = sigf(ar[nt*4+2] + br.x), r3 = sigf(ar[nt*4+3] + br.y);
            *(float2*)&sm->X[row0][c0] = make_float2(rna_tf32(r0 * h01.x), rna_tf32(r1 * h01.y));
            *(float2*)&sm->X[row1][c0] = make_float2(rna_tf32(r2 * h23.x), rna_tf32(r3 * h23.y));
            az[nt*4+0] = z0; az[nt*4+1] = z1; az[nt*4+2] = z2; az[nt*4+3] = z3;
            ar[nt*4+0] = h01.x; ar[nt*4+1] = h01.y; ar[nt*4+2] = h23.x; ar[nt*4+3] = h23.y;
        }
        barpair(tile);   // H*R from both warps visible

        // ---- h GEMM ----
        float ah[16];
#pragma unroll
        for (int i = 0; i < 16; i++) ah[i] = 0.0f;
#pragma unroll
        for (int kb = 0; kb < 9; kb++) {
            float2 va = *(float2*)&sm->X[row0][kb * 8 + 2 * tig];
            float2 vb = *(float2*)&sm->X[row1][kb * 8 + 2 * tig];
            u32 a0 = __float_as_uint(va.x), a2 = __float_as_uint(va.y);
            u32 a1 = __float_as_uint(vb.x), a3 = __float_as_uint(vb.y);
#pragma unroll
            for (int nt = 0; nt < 4; nt++) {
                float2 b = sm->WH[kb][ntb + nt][lane];
                mma8(ah + nt * 4, a0, a1, a2, a3, __float_as_uint(b.x), __float_as_uint(b.y));
            }
        }

        // ---- epilogue 2 ----
#pragma unroll
        for (int nt = 0; nt < 4; nt++) {
            int c0 = (ntb + nt) * 8 + tig * 2;
            float2 bh = *(float2*)&sm->BP[2][c0];
            float hn[4];
#pragma unroll
            for (int q = 0; q < 4; q++) {
                float bb = (q & 1) ? bh.y : bh.x;
                float ht = tanha(ah[nt*4+q] + bb);
                float z = az[nt*4+q], hd = ar[nt*4+q];
                float v = z * hd + (1.0f - z) * ht;
                hacc[nt*4+q] = fmaf(p, v, hacc[nt*4+q]);
                hn[q] = rna_tf32(v);
            }
            *(float2*)&sm->X[row0][c0] = make_float2(hn[0], hn[1]);
            *(float2*)&sm->X[row1][c0] = make_float2(hn[2], hn[3]);
        }
        barpair(tile);   // epi2 done before next stage/GEMM
    }

    // ---- head ----
#pragma unroll
    for (int nt = 0; nt < 4; nt++) {
        int c0 = (ntb + nt) * 8 + tig * 2;
        *(float2*)&sm->X[row0][c0] =
            make_float2(fmaxf(hacc[nt*4+0], 0.f), fmaxf(hacc[nt*4+1], 0.f));
        *(float2*)&sm->X[row1][c0] =
            make_float2(fmaxf(hacc[nt*4+2], 0.f), fmaxf(hacc[nt*4+3], 0.f));
    }
    __syncthreads();

    float* sW = (float*)&sm->WZR[0][0][0];
    float* sB = &sm->BP[0][0];
    for (int i = tid; i < OUT * PERIODS; i += THR) sW[i] = hw[i];
    if (tid < PERIODS) sB[tid] = hb[tid];
    __syncthreads();

    for (int i = tid; i < MB2 * PERIODS; i += THR) {
        int nn = i / PERIODS, pp = i - nn * PERIODS;
        int node = nb + nn;
        if (node >= N_NODES) continue;
        float acc = sB[pp];
#pragma unroll 16
        for (int o = 0; o < OUT; o++)
            acc = fmaf(sm->X[nn][o], sW[o * PERIODS + pp], acc);
        out[node * PERIODS + pp] = acc;
    }
}

extern "C" void kernel_launch(void* const* d_in, const int* in_sizes, int n_in,
                              void* d_out, int out_size) {
    const float* x   = (const float*)d_in[0];
    const int*   ei  = (const int*)d_in[1];
    const float* Wz  = (const float*)d_in[2];
    const float* bz  = (const float*)d_in[3];
    const float* LzW = (const float*)d_in[4];
    const float* Lzb = (const float*)d_in[5];
    const float* Wr  = (const float*)d_in[6];
    const float* br  = (const float*)d_in[7];
    const float* LrW = (const float*)d_in[8];
    const float* Lrb = (const float*)d_in[9];
    const float* Wh  = (const float*)d_in[10];
    const float* bh  = (const float*)d_in[11];
    const float* LhW = (const float*)d_in[12];
    const float* Lhb = (const float*)d_in[13];
    const float* att = (const float*)d_in[14];
    const float* hW  = (const float*)d_in[15];
    const float* hb  = (const float*)d_in[16];
    float* out = (float*)d_out;

    cudaFuncSetAttribute(k_fused, cudaFuncAttributeMaxDynamicSharedMemorySize, (int)sizeof(FS2));

    k_init<<<(N_NODES + 255) / 256, 256>>>(Wz, bz, LzW, Lzb, Wr, br, LrW, Lrb,
                                           Wh, bh, LhW, Lhb, att);
    k_fill<<<(N_EDGES + 255) / 256, 256>>>(ei);
    k_gather<<<(N_NODES * 32 + 255) / 256, 256>>>(x);
    k_fused<<<(N_NODES + MB2 - 1) / MB2, THR, sizeof(FS2)>>>(LzW, LrW, LhW, hW, hb, out);
}